// round 12
// baseline (speedup 1.0000x reference)
#include <cuda_runtime.h>
#include <cuda_fp16.h>
#include <cuda_bf16.h>
#include <math.h>
#include <stdint.h>

#define NPOS 16384          // H*W
#define NB   16             // batch
#define NCH  128            // C == hidden
#define NTILE (NB * NPOS / 64)   // 4096 64-row tiles

// ---------------- device scratch (allocation-free rule: __device__ globals) ----
__device__ uint32_t g_q   [NTILE * 4096];   // q fp16 pairs, swizzled 64x128 tiles
__device__ uint32_t g_part[NTILE * 2176];   // per tile: 2048 bf16x2 ctx + 128 f32 se
__device__ float    g_ctx [NB * 4224];      // reduced per batch (4096 ctx + 128 se)
__device__ uint32_t g_W2  [NB * 8192];      // fused W2 fp16, swizzled 128x128 per b
__device__ uint32_t g_wsw [3 * 8192];       // w_qkv fp16, 3 swizzled 128x128 chunks

// ---------------- helpers -------------------------------------------------------
__device__ __forceinline__ uint32_t smem_u32(const void* p) {
    uint32_t a;
    asm("{ .reg .u64 t; cvta.to.shared.u64 t, %1; cvt.u32.u64 %0, t; }" : "=r"(a) : "l"(p));
    return a;
}
// swizzled byte offset within a 128-col b16 tile (256B rows)
__device__ __forceinline__ uint32_t toff(int r, int c) {
    return (uint32_t)(r * 256 + (((c >> 3) ^ (r & 7)) << 4) + ((c & 7) << 1));
}
// swizzled byte offset within a 64-col b16 tile (128B rows)
__device__ __forceinline__ uint32_t toff64(int r, int c) {
    return (uint32_t)(r * 128 + (((c >> 3) ^ (r & 7)) << 4) + ((c & 7) << 1));
}
__device__ __forceinline__ void ldsm4(uint32_t* r, uint32_t a) {
    asm volatile("ldmatrix.sync.aligned.m8n8.x4.shared.b16 {%0,%1,%2,%3}, [%4];"
                 : "=r"(r[0]), "=r"(r[1]), "=r"(r[2]), "=r"(r[3]) : "r"(a));
}
__device__ __forceinline__ void ldsm4t(uint32_t* r, uint32_t a) {
    asm volatile("ldmatrix.sync.aligned.m8n8.x4.trans.shared.b16 {%0,%1,%2,%3}, [%4];"
                 : "=r"(r[0]), "=r"(r[1]), "=r"(r[2]), "=r"(r[3]) : "r"(a));
}
__device__ __forceinline__ void mma16816(float* d, const uint32_t* a, uint32_t b0, uint32_t b1) {
    asm volatile(
        "mma.sync.aligned.m16n8k16.row.col.f32.f16.f16.f32 "
        "{%0,%1,%2,%3}, {%4,%5,%6,%7}, {%8,%9}, {%0,%1,%2,%3};"
        : "+f"(d[0]), "+f"(d[1]), "+f"(d[2]), "+f"(d[3])
        : "r"(a[0]), "r"(a[1]), "r"(a[2]), "r"(a[3]), "r"(b0), "r"(b1));
}
__device__ __forceinline__ uint32_t pack_h2(float a, float b) {
    __half2 h = __floats2half2_rn(a, b);
    return *(uint32_t*)&h;
}
__device__ __forceinline__ void split_h(float v0, float v1, uint32_t& hi, uint32_t& lo) {
    __half2 h = __floats2half2_rn(v0, v1);
    float2 hf = __half22float2(h);
    __half2 l = __floats2half2_rn(v0 - hf.x, v1 - hf.y);
    hi = *(uint32_t*)&h;
    lo = *(uint32_t*)&l;
}
__device__ __forceinline__ void cp_async16(uint32_t smem_dst, const void* gsrc) {
    asm volatile("cp.async.cg.shared.global [%0], [%1], 16;" :: "r"(smem_dst), "l"(gsrc));
}

// =============================================================================
// K0: convert w_qkv to fp16, pre-swizzled, 3 chunks of 128x128
// =============================================================================
__global__ __launch_bounds__(256)
void k_prep(const float* __restrict__ w_qkv)
{
    int idx = blockIdx.x * 256 + threadIdx.x;   // 24576 items
    int chunk = idx >> 13, rem = idx & 8191;
    int o = rem >> 6, cp = rem & 63;
    int c0 = cp * 2;
    float v0 = w_qkv[(size_t)(chunk * 128 + o) * NCH + c0];
    float v1 = w_qkv[(size_t)(chunk * 128 + o) * NCH + c0 + 1];
    g_wsw[(uint32_t)chunk * 8192 + (toff(o, c0) >> 2)] = pack_h2(v0, v1);
}

// =============================================================================
// K1: fused qkv-GEMM (fp16) + q-softmax + ctx partial.  A (x) fragments are
// loaded ONCE into registers and reused across all 3 chunks.
// 64 positions/block, 4096 blocks, 2 CTAs/SM.
// smem: X 16K (x -> v_hi) | W 32K (w chunk -> ctx red staging) |
//       EKH 16K | EKL 16K | VL 16K | SE 1K  = 97 KB
// =============================================================================
#define Q_X   0
#define Q_W   16384
#define Q_EKH 49152
#define Q_EKL 65536
#define Q_VL  81920
#define Q_SE  98304
#define Q_SMEM 99328

__global__ __launch_bounds__(256, 2)
void k_qkv(const float* __restrict__ x)
{
    extern __shared__ char smc[];
    const uint32_t sb = smem_u32(smc);
    const int tid = threadIdx.x;
    const int warp = tid >> 5, lane = tid & 31;
    const int wm = warp & 1, wn = warp >> 1;        // wm: 2x32 pos, wn: 4x32 ch

    const int b    = blockIdx.x >> 8;
    const int tile = blockIdx.x & 255;
    const int n0   = tile << 6;
    const uint32_t gt = (uint32_t)blockIdx.x;

    // ---- load x tile [c=128][p=64] as fp16, toff64 swizzle; w chunk0 copy ----
    {
        const float* xb = x + (size_t)b * NCH * NPOS + n0;
#pragma unroll
        for (int i = 0; i < 8; i++) {
            int lin = tid + i * 256;            // 2048 float4
            int c = lin >> 4, pq = lin & 15;
            float4 v = *(const float4*)(xb + (size_t)c * NPOS + pq * 4);
            uint32_t o = toff64(c, pq * 4);
            *(uint32_t*)(smc + Q_X + o)     = pack_h2(v.x, v.y);
            *(uint32_t*)(smc + Q_X + o + 4) = pack_h2(v.z, v.w);
        }
#pragma unroll
        for (int i = 0; i < 8; i++) {
            int lin = tid + i * 256;            // 2048 uint4
            ((uint4*)(smc + Q_W))[lin] = ((const uint4*)g_wsw)[lin];
        }
    }
    __syncthreads();

    const int l7 = lane & 7, lb3 = (lane >> 3) & 1, lb4 = (lane >> 4) & 1;
    const float scale = 0.17677669529663687f;   // 32^-0.5

    // ---- cache ALL x A-fragments in registers (reused by every chunk) ----
    uint32_t afr[8][2][4];
#pragma unroll
    for (int k = 0; k < 8; k++)
#pragma unroll
        for (int mt = 0; mt < 2; mt++)
            ldsm4t(afr[k][mt], sb + Q_X + toff64(k * 16 + l7 + lb4 * 8,
                                                 wm * 32 + mt * 16 + lb3 * 8));

    for (int chunk = 0; chunk < 3; chunk++) {
        float acc[2][4][4];
#pragma unroll
        for (int mt = 0; mt < 2; mt++)
#pragma unroll
            for (int u = 0; u < 4; u++)
#pragma unroll
                for (int r = 0; r < 4; r++) acc[mt][u][r] = 0.f;

        // single fp16 pass: only B-side ldsm needed
#pragma unroll
        for (int k = 0; k < 8; k++) {
            uint32_t bfr[2][4];
#pragma unroll
            for (int nt = 0; nt < 2; nt++)
                ldsm4(bfr[nt], sb + Q_W + toff(wn * 32 + nt * 16 + l7 + lb4 * 8, k * 16 + lb3 * 8));
#pragma unroll
            for (int mt = 0; mt < 2; mt++)
#pragma unroll
                for (int u = 0; u < 4; u++)
                    mma16816(acc[mt][u], afr[k][mt], bfr[u >> 1][(u & 1) * 2],
                             bfr[u >> 1][(u & 1) * 2 + 1]);
        }
        __syncthreads();   // all MMA reads of Q_W complete

        // prefetch next w chunk into Q_W, overlapped with the epilogue below
        if (chunk < 2) {
#pragma unroll
            for (int i = 0; i < 8; i++) {
                int lin = tid + i * 256;
                cp_async16(sb + Q_W + lin * 16, ((const uint4*)g_wsw) + (chunk + 1) * 2048 + lin);
            }
            asm volatile("cp.async.commit_group;");
        }

        // ---- epilogues ----
        if (chunk == 0) {
            // q: softmax over 32 channels per head -> global fp16 swizzled tiles
#pragma unroll
            for (int mt = 0; mt < 2; mt++)
#pragma unroll
            for (int h8 = 0; h8 < 2; h8++) {
                float e[4][2];
                float s = 0.f;
#pragma unroll
                for (int u = 0; u < 4; u++)
#pragma unroll
                    for (int j = 0; j < 2; j++) {
                        float v = __expf(acc[mt][u][h8 * 2 + j]);
                        e[u][j] = v;
                        s += v;
                    }
                s += __shfl_xor_sync(0xffffffffu, s, 1);
                s += __shfl_xor_sync(0xffffffffu, s, 2);
                const float inv = scale / s;
                const int p = wm * 32 + mt * 16 + h8 * 8 + (lane >> 2);
#pragma unroll
                for (int u = 0; u < 4; u++) {
                    int ch0 = wn * 32 + u * 8 + (lane & 3) * 2;
                    g_q[gt * 4096 + (toff(p, ch0) >> 2)] = pack_h2(e[u][0] * inv, e[u][1] * inv);
                }
            }
        } else if (chunk == 1) {
            // ek = exp(k): split fp16 into EKH/EKL; sumexp partials (f32 exact)
            float sep[4][2];
#pragma unroll
            for (int u = 0; u < 4; u++) { sep[u][0] = 0.f; sep[u][1] = 0.f; }
#pragma unroll
            for (int mt = 0; mt < 2; mt++)
#pragma unroll
            for (int h8 = 0; h8 < 2; h8++) {
                const int p = wm * 32 + mt * 16 + h8 * 8 + (lane >> 2);
#pragma unroll
                for (int u = 0; u < 4; u++) {
                    float v0 = __expf(acc[mt][u][h8 * 2]);
                    float v1 = __expf(acc[mt][u][h8 * 2 + 1]);
                    sep[u][0] += v0; sep[u][1] += v1;
                    uint32_t hi, lo;
                    split_h(v0, v1, hi, lo);
                    int ch0 = wn * 32 + u * 8 + (lane & 3) * 2;
                    uint32_t o = toff(p, ch0);
                    *(uint32_t*)(smc + Q_EKH + o) = hi;
                    *(uint32_t*)(smc + Q_EKL + o) = lo;
                }
            }
            float* se = (float*)(smc + Q_SE);
#pragma unroll
            for (int u = 0; u < 4; u++)
#pragma unroll
                for (int j = 0; j < 2; j++) {
                    float s = sep[u][j];
                    s += __shfl_xor_sync(0xffffffffu, s, 4);
                    s += __shfl_xor_sync(0xffffffffu, s, 8);
                    s += __shfl_xor_sync(0xffffffffu, s, 16);
                    if ((lane >> 2) == 0)
                        se[warp * 32 + u * 8 + (lane & 3) * 2 + j] = s;
                }
        } else {
            // v: split fp16 -> X (v_hi) + VL (v_lo); A frags live in registers
#pragma unroll
            for (int mt = 0; mt < 2; mt++)
#pragma unroll
            for (int h8 = 0; h8 < 2; h8++) {
                const int p = wm * 32 + mt * 16 + h8 * 8 + (lane >> 2);
#pragma unroll
                for (int u = 0; u < 4; u++) {
                    uint32_t hi, lo;
                    split_h(acc[mt][u][h8 * 2], acc[mt][u][h8 * 2 + 1], hi, lo);
                    int ch0 = wn * 32 + u * 8 + (lane & 3) * 2;
                    uint32_t o = toff(p, ch0);
                    *(uint32_t*)(smc + Q_X + o)  = hi;
                    *(uint32_t*)(smc + Q_VL + o) = lo;
                }
            }
        }

        if (chunk < 2) asm volatile("cp.async.wait_group 0;" ::: "memory");
        __syncthreads();
    }

    // ---- ctx partial: ctx_h[d][e] = sum_p ek[p,d] v[p,e]  (3 split passes) ----
    const int h = warp & 3, ks = warp >> 2;
    float ctx[2][4][4];
#pragma unroll
    for (int mt = 0; mt < 2; mt++)
#pragma unroll
        for (int u = 0; u < 4; u++)
#pragma unroll
            for (int r = 0; r < 4; r++) ctx[mt][u][r] = 0.f;

    {
        const int PA[3] = {Q_EKH, Q_EKH, Q_EKL};
        const int PB[3] = {Q_X,   Q_VL,  Q_X};
#pragma unroll
        for (int ps = 0; ps < 3; ps++) {
            const uint32_t aB = sb + PA[ps], bB = sb + PB[ps];
#pragma unroll
            for (int kk = 0; kk < 2; kk++) {
                const int p0 = ks * 32 + kk * 16;
                uint32_t a[2][4];
#pragma unroll
                for (int mt = 0; mt < 2; mt++)
                    ldsm4t(a[mt], aB + toff(p0 + l7 + lb4 * 8, h * 32 + mt * 16 + lb3 * 8));
                uint32_t bfr[2][4];
#pragma unroll
                for (int nt = 0; nt < 2; nt++)
                    ldsm4t(bfr[nt], bB + toff(p0 + l7 + lb3 * 8, h * 32 + nt * 16 + lb4 * 8));
#pragma unroll
                for (int mt = 0; mt < 2; mt++)
#pragma unroll
                    for (int u = 0; u < 4; u++)
                        mma16816(ctx[mt][u], a[mt], bfr[u >> 1][(u & 1) * 2],
                                 bfr[u >> 1][(u & 1) * 2 + 1]);
            }
        }
    }

    // two-phase ctx staging into 16KB red buffer (aliases Q_W)
    float* rb = (float*)(smc + Q_W);
    __syncthreads();
    if (ks == 0) {
#pragma unroll
        for (int mt = 0; mt < 2; mt++)
#pragma unroll
            for (int u = 0; u < 4; u++) {
                int dr = mt * 16 + (lane >> 2), e = u * 8 + (lane & 3) * 2;
                float* r = rb + h * 1024;
                r[dr * 32 + e]           = ctx[mt][u][0];
                r[dr * 32 + e + 1]       = ctx[mt][u][1];
                r[(dr + 8) * 32 + e]     = ctx[mt][u][2];
                r[(dr + 8) * 32 + e + 1] = ctx[mt][u][3];
            }
    }
    __syncthreads();
    if (ks == 1) {
#pragma unroll
        for (int mt = 0; mt < 2; mt++)
#pragma unroll
            for (int u = 0; u < 4; u++) {
                int dr = mt * 16 + (lane >> 2), e = u * 8 + (lane & 3) * 2;
                float* r = rb + h * 1024;
                r[dr * 32 + e]           += ctx[mt][u][0];
                r[dr * 32 + e + 1]       += ctx[mt][u][1];
                r[(dr + 8) * 32 + e]     += ctx[mt][u][2];
                r[(dr + 8) * 32 + e + 1] += ctx[mt][u][3];
            }
    }
    __syncthreads();

    // ---- write block partial: 2048 bf16x2 ctx + 128 f32 se ----
    {
        const size_t pbase = (size_t)gt * 2176;
#pragma unroll
        for (int i = 0; i < 8; i++) {
            int idx = tid + i * 256;            // 2048
            __nv_bfloat162 pkt = __float22bfloat162_rn(make_float2(rb[idx * 2], rb[idx * 2 + 1]));
            g_part[pbase + idx] = *(uint32_t*)&pkt;
        }
        if (tid < 128) {
            const float* se = (const float*)(smc + Q_SE);
            int wq = tid >> 5;
            float s = se[(wq * 2) * 32 + (tid & 31)] + se[(wq * 2 + 1) * 32 + (tid & 31)];
            g_part[pbase + 2048 + tid] = __float_as_uint(s);
        }
    }
}

// =============================================================================
// K2: reduce 256 tile partials per batch -> g_ctx[b][4224]
// =============================================================================
__global__ __launch_bounds__(128, 8)
void k_red()
{
    const int b = blockIdx.x / 17, g = blockIdx.x % 17;
    const int col = g * 128 + threadIdx.x;      // 0..2175
    const uint32_t* src = g_part + (size_t)b * 256 * 2176 + col;
    if (col < 2048) {
        float s0 = 0.f, s1 = 0.f;
#pragma unroll 4
        for (int t = 0; t < 256; t++) {
            uint32_t u = src[(size_t)t * 2176];
            float2 f = __bfloat1622float2(*(__nv_bfloat162*)&u);
            s0 += f.x; s1 += f.y;
        }
        g_ctx[b * 4224 + col * 2]     = s0;
        g_ctx[b * 4224 + col * 2 + 1] = s1;
    } else {
        float s = 0.f;
#pragma unroll 4
        for (int t = 0; t < 256; t++)
            s += __uint_as_float(src[(size_t)t * 2176]);
        g_ctx[b * 4224 + 4096 + (col - 2048)] = s;
    }
}

// =============================================================================
// K3: normalize ctx, build fused W2 (fp16), swizzled tiles per b.
// grid = NB*32 (4 c-rows per block).
// =============================================================================
__global__ __launch_bounds__(256, 4)
void k_w2(const float* __restrict__ w_out)
{
    __shared__ float ctxs[4224];     // [h][d][33]
    __shared__ float Ss[128];
    __shared__ float ws2[512];       // 4 c-rows x 128 ch

    const int b  = blockIdx.x >> 5;
    const int c0 = (blockIdx.x & 31) * 4;
    const int tid = threadIdx.x;

    for (int lin = tid; lin < 512; lin += 256)
        ws2[lin] = w_out[(size_t)(c0 + (lin >> 7)) * 128 + (lin & 127)];
    for (int idx = tid; idx < 4096; idx += 256) {
        int h = idx >> 10, de = idx & 1023;
        ctxs[h * 1056 + (de >> 5) * 33 + (de & 31)] = g_ctx[b * 4224 + idx];
    }
    if (tid < 128) Ss[tid] = 1.0f / g_ctx[b * 4224 + 4096 + tid];
    __syncthreads();

    {
        int cl = tid >> 6, cpp = tid & 63;       // 256 threads = 4 rows x 64 pairs
        int ch0 = cpp * 2;
        int h = ch0 >> 5, d = ch0 & 31;
        const float* cr0 = &ctxs[h * 1056 + d * 33];
        const float* cr1 = cr0 + 33;
        const float* wr  = &ws2[cl * 128 + h * 32];
        float a0 = 0.f, a1 = 0.f;
#pragma unroll
        for (int e = 0; e < 32; e++) {
            a0 = fmaf(wr[e], cr0[e], a0);
            a1 = fmaf(wr[e], cr1[e], a1);
        }
        g_W2[(uint32_t)b * 8192 + (toff(c0 + cl, ch0) >> 2)] =
            pack_h2(a0 * Ss[ch0], a1 * Ss[ch0 + 1]);
    }
}

// =============================================================================
// K4: y = W2_b @ q + b_out via fp16 mma, LayerNorm fused.  4 q-tiles per block
// (W2 loaded once), grid 1024, 2 CTAs/SM.  smem ~98.5 KB.
// =============================================================================
#define K3_W   0
#define K3_Q0  32768
#define K3_RS  98304
#define K3_RQ  99328
#define K3_MU  100352
#define K3_RST 100608
#define K3_SMEM 100864

__global__ __launch_bounds__(256, 2)
void k_out(const float* __restrict__ b_out, const float* __restrict__ ln_g,
           const float* __restrict__ ln_b, float* __restrict__ out)
{
    extern __shared__ char smc[];
    const uint32_t sb = smem_u32(smc);
    float* red_s = (float*)(smc + K3_RS);    // [4][64]
    float* red_q = (float*)(smc + K3_RQ);    // [4][64]
    float* mu_s  = (float*)(smc + K3_MU);    // [64]
    float* rs_s  = (float*)(smc + K3_RST);   // [64]

    const int tid = threadIdx.x;
    const int warp = tid >> 5, lane = tid & 31;
    const int wm = warp & 3, wn = warp >> 2;          // wn in {0,1}
    const int b  = blockIdx.x >> 6;
    const int tq = blockIdx.x & 63;                   // group of 4 tiles
    const size_t qt0 = ((size_t)b * 256 + tq * 4) * 1024;   // uint4 base, tile 0

#pragma unroll
    for (int i = 0; i < 8; i++) {
        int lin = tid + i * 256;              // 2048 uint4: W2 tile
        ((uint4*)(smc + K3_W))[lin] = ((const uint4*)g_W2)[(size_t)b * 2048 + lin];
    }
#pragma unroll
    for (int i = 0; i < 16; i++) {
        int lin = tid + i * 256;              // 4096 uint4: four q tiles
        ((uint4*)(smc + K3_Q0))[lin] = ((const uint4*)g_q)[qt0 + lin];
    }
    __syncthreads();

    const int l7 = lane & 7, lb3 = (lane >> 3) & 1, lb4 = (lane >> 4) & 1;

    // hoist per-channel constants (fixed per warp across tiles)
    float bo_r[2][2], g_r[2][2], bb_r[2][2];
#pragma unroll
    for (int mt = 0; mt < 2; mt++)
#pragma unroll
        for (int h8 = 0; h8 < 2; h8++) {
            int c = wm * 32 + mt * 16 + h8 * 8 + (lane >> 2);
            bo_r[mt][h8] = b_out[c];
            g_r[mt][h8]  = ln_g[c];
            bb_r[mt][h8] = ln_b[c];
        }

    for (int t2 = 0; t2 < 4; t2++) {
        const int n0 = (tq * 4 + t2) << 6;
        const uint32_t qB = sb + K3_Q0 + t2 * 16384;

        float acc[2][4][4];
#pragma unroll
        for (int mt = 0; mt < 2; mt++)
#pragma unroll
            for (int u = 0; u < 4; u++)
#pragma unroll
                for (int r = 0; r < 4; r++) acc[mt][u][r] = 0.f;

#pragma unroll
        for (int k = 0; k < 8; k++) {
            uint32_t a[2][4];
#pragma unroll
            for (int mt = 0; mt < 2; mt++)
                ldsm4(a[mt], sb + K3_W + toff(wm * 32 + mt * 16 + l7 + lb3 * 8, k * 16 + lb4 * 8));
            uint32_t bfr[2][4];
#pragma unroll
            for (int nt = 0; nt < 2; nt++)
                ldsm4(bfr[nt], qB + toff(wn * 32 + nt * 16 + l7 + lb4 * 8, k * 16 + lb3 * 8));
#pragma unroll
            for (int mt = 0; mt < 2; mt++)
#pragma unroll
                for (int u = 0; u < 4; u++)
                    mma16816(acc[mt][u], a[mt], bfr[u >> 1][(u & 1) * 2], bfr[u >> 1][(u & 1) * 2 + 1]);
        }

        // bias
#pragma unroll
        for (int mt = 0; mt < 2; mt++)
#pragma unroll
            for (int h8 = 0; h8 < 2; h8++) {
                const float bo = bo_r[mt][h8];
#pragma unroll
                for (int u = 0; u < 4; u++) {
                    acc[mt][u][h8 * 2]     += bo;
                    acc[mt][u][h8 * 2 + 1] += bo;
                }
            }

        // LN partials
#pragma unroll
        for (int u = 0; u < 4; u++)
#pragma unroll
            for (int j = 0; j < 2; j++) {
                float a0 = acc[0][u][j],     a1 = acc[0][u][2 + j];
                float a2 = acc[1][u][j],     a3 = acc[1][u][2 + j];
                float s = a0 + a1 + a2 + a3;
                float q = a0 * a0 + a1 * a1 + a2 * a2 + a3 * a3;
                s += __shfl_xor_sync(0xffffffffu, s, 4);
                q += __shfl_xor_sync(0xffffffffu, q, 4);
                s += __shfl_xor_sync(0xffffffffu, s, 8);
                q += __shfl_xor_sync(0xffffffffu, q, 8);
                s += __shfl_xor_sync(0xffffffffu, s, 16);
                q += __shfl_xor_sync(0xffffffffu, q, 16);
                if ((lane >> 2) == 0) {
                    int col = wn * 32 + u * 8 + (lane & 3) * 2 + j;
                    red_s[wm * 64 + col] = s;
                    red_q[wm * 64 + col] = q;
                }
            }
        __syncthreads();

        if (tid < 64) {
            float s = red_s[tid] + red_s[64 + tid] + red_s[128 + tid] + red_s[192 + tid];
            float q = red_q[tid] + red_q[64 + tid] + red_q[128 + tid] + red_q[192 + tid];
            float mu  = s * (1.0f / 128.0f);
            float var = q * (1.0f / 128.0f) - mu * mu;
            mu_s[tid] = mu;
            rs_s[tid] = rsqrtf(var + 1e-5f);
        }
        __syncthreads();

#pragma unroll
        for (int mt = 0; mt < 2; mt++)
#pragma unroll
            for (int h8 = 0; h8 < 2; h8++) {
                const int c = wm * 32 + mt * 16 + h8 * 8 + (lane >> 2);
                const float g  = g_r[mt][h8];
                const float bb = bb_r[mt][h8];
                float* rowp = out + ((size_t)b * NCH + c) * NPOS + n0 + wn * 32 + (lane & 3) * 2;
#pragma unroll
                for (int u = 0; u < 4; u++) {
                    int col = wn * 32 + u * 8 + (lane & 3) * 2;
                    float v0 = (acc[mt][u][h8 * 2]     - mu_s[col])     * rs_s[col]     * g + bb;
                    float v1 = (acc[mt][u][h8 * 2 + 1] - mu_s[col + 1]) * rs_s[col + 1] * g + bb;
                    *(float2*)(rowp + u * 8) = make_float2(v0, v1);
                }
            }
        __syncthreads();   // red/mu buffers reused by next tile
    }
}

// =============================================================================
extern "C" void kernel_launch(void* const* d_in, const int* in_sizes, int n_in,
                              void* d_out, int out_size)
{
    const float* x     = (const float*)d_in[0];
    const float* w_qkv = (const float*)d_in[1];
    const float* w_out = (const float*)d_in[2];
    const float* b_out = (const float*)d_in[3];
    const float* ln_g  = (const float*)d_in[4];
    const float* ln_b  = (const float*)d_in[5];
    float* out = (float*)d_out;

    cudaFuncSetAttribute(k_qkv, cudaFuncAttributeMaxDynamicSharedMemorySize, Q_SMEM);
    cudaFuncSetAttribute(k_out, cudaFuncAttributeMaxDynamicSharedMemorySize, K3_SMEM);

    k_prep<<<96, 256>>>(w_qkv);
    k_qkv<<<4096, 256, Q_SMEM>>>(x);
    k_red<<<272, 128>>>();
    k_w2<<<512, 256>>>(w_out);
    k_out<<<1024, 256, K3_SMEM>>>(b_out, ln_g, ln_b, out);
}

// round 13
// speedup vs baseline: 1.1056x; 1.1056x over previous
#include <cuda_runtime.h>
#include <cuda_fp16.h>
#include <cuda_bf16.h>
#include <math.h>
#include <stdint.h>

#define NPOS 16384          // H*W
#define NB   16             // batch
#define NCH  128            // C == hidden
#define NTILE (NB * NPOS / 64)   // 4096 64-row tiles

// ---------------- device scratch (allocation-free rule: __device__ globals) ----
__device__ uint32_t g_q   [NTILE * 4096];   // q fp16 pairs, swizzled 64x128 tiles
__device__ uint32_t g_part[NTILE * 2176];   // per tile: 2048 bf16x2 ctx + 128 f32 se
__device__ float    g_ctx [NB * 4224];      // reduced per batch (4096 ctx + 128 se)
__device__ uint32_t g_W2  [NB * 8192];      // fused W2 fp16, swizzled 128x128 per b
__device__ uint32_t g_wsw [3 * 8192];       // w_qkv fp16, 3 swizzled 128x128 chunks

// ---------------- helpers -------------------------------------------------------
__device__ __forceinline__ uint32_t smem_u32(const void* p) {
    uint32_t a;
    asm("{ .reg .u64 t; cvta.to.shared.u64 t, %1; cvt.u32.u64 %0, t; }" : "=r"(a) : "l"(p));
    return a;
}
// swizzled byte offset within a 128-col b16 tile (256B rows)
__device__ __forceinline__ uint32_t toff(int r, int c) {
    return (uint32_t)(r * 256 + (((c >> 3) ^ (r & 7)) << 4) + ((c & 7) << 1));
}
// swizzled byte offset within a 64-col b16 tile (128B rows)
__device__ __forceinline__ uint32_t toff64(int r, int c) {
    return (uint32_t)(r * 128 + (((c >> 3) ^ (r & 7)) << 4) + ((c & 7) << 1));
}
__device__ __forceinline__ void ldsm4(uint32_t* r, uint32_t a) {
    asm volatile("ldmatrix.sync.aligned.m8n8.x4.shared.b16 {%0,%1,%2,%3}, [%4];"
                 : "=r"(r[0]), "=r"(r[1]), "=r"(r[2]), "=r"(r[3]) : "r"(a));
}
__device__ __forceinline__ void ldsm4t(uint32_t* r, uint32_t a) {
    asm volatile("ldmatrix.sync.aligned.m8n8.x4.trans.shared.b16 {%0,%1,%2,%3}, [%4];"
                 : "=r"(r[0]), "=r"(r[1]), "=r"(r[2]), "=r"(r[3]) : "r"(a));
}
__device__ __forceinline__ void mma16816(float* d, const uint32_t* a, uint32_t b0, uint32_t b1) {
    asm volatile(
        "mma.sync.aligned.m16n8k16.row.col.f32.f16.f16.f32 "
        "{%0,%1,%2,%3}, {%4,%5,%6,%7}, {%8,%9}, {%0,%1,%2,%3};"
        : "+f"(d[0]), "+f"(d[1]), "+f"(d[2]), "+f"(d[3])
        : "r"(a[0]), "r"(a[1]), "r"(a[2]), "r"(a[3]), "r"(b0), "r"(b1));
}
__device__ __forceinline__ uint32_t pack_h2(float a, float b) {
    __half2 h = __floats2half2_rn(a, b);
    return *(uint32_t*)&h;
}
__device__ __forceinline__ void cp_async16(uint32_t smem_dst, const void* gsrc) {
    asm volatile("cp.async.cg.shared.global [%0], [%1], 16;" :: "r"(smem_dst), "l"(gsrc));
}

// =============================================================================
// K0: convert w_qkv to fp16, pre-swizzled, 3 chunks of 128x128
// =============================================================================
__global__ __launch_bounds__(256)
void k_prep(const float* __restrict__ w_qkv)
{
    int idx = blockIdx.x * 256 + threadIdx.x;   // 24576 items
    int chunk = idx >> 13, rem = idx & 8191;
    int o = rem >> 6, cp = rem & 63;
    int c0 = cp * 2;
    float v0 = w_qkv[(size_t)(chunk * 128 + o) * NCH + c0];
    float v1 = w_qkv[(size_t)(chunk * 128 + o) * NCH + c0 + 1];
    g_wsw[(uint32_t)chunk * 8192 + (toff(o, c0) >> 2)] = pack_h2(v0, v1);
}

// =============================================================================
// K1: fused qkv-GEMM (fp16 single-pass) + q-softmax + ctx partial (fp16 single:
// ek and v kept in ONE fp16 copy — error budget allows it).
// 64 positions/block, 4096 blocks.  cp.async prefetch of next w chunk.
// smem: X 16K (x -> v) | W 32K (w chunk -> ctx red staging) | EK 16K | SE 1K
//       = 65 KB  (up to 3 CTAs/SM if regs permit)
// =============================================================================
#define Q_X   0
#define Q_W   16384
#define Q_EK  49152
#define Q_SE  65536
#define Q_SMEM 66560

__global__ __launch_bounds__(256, 2)
void k_qkv(const float* __restrict__ x)
{
    extern __shared__ char smc[];
    const uint32_t sb = smem_u32(smc);
    const int tid = threadIdx.x;
    const int warp = tid >> 5, lane = tid & 31;
    const int wm = warp & 1, wn = warp >> 1;        // wm: 2x32 pos, wn: 4x32 ch

    const int b    = blockIdx.x >> 8;
    const int tile = blockIdx.x & 255;
    const int n0   = tile << 6;
    const uint32_t gt = (uint32_t)blockIdx.x;

    // ---- load x tile [c=128][p=64] as fp16, toff64 swizzle; w chunk0 copy ----
    {
        const float* xb = x + (size_t)b * NCH * NPOS + n0;
#pragma unroll
        for (int i = 0; i < 8; i++) {
            int lin = tid + i * 256;            // 2048 float4
            int c = lin >> 4, pq = lin & 15;
            float4 v = *(const float4*)(xb + (size_t)c * NPOS + pq * 4);
            uint32_t o = toff64(c, pq * 4);
            *(uint32_t*)(smc + Q_X + o)     = pack_h2(v.x, v.y);
            *(uint32_t*)(smc + Q_X + o + 4) = pack_h2(v.z, v.w);
        }
#pragma unroll
        for (int i = 0; i < 8; i++) {
            int lin = tid + i * 256;            // 2048 uint4
            ((uint4*)(smc + Q_W))[lin] = ((const uint4*)g_wsw)[lin];
        }
    }
    __syncthreads();

    const int l7 = lane & 7, lb3 = (lane >> 3) & 1, lb4 = (lane >> 4) & 1;
    const float scale = 0.17677669529663687f;   // 32^-0.5

    for (int chunk = 0; chunk < 3; chunk++) {
        float acc[2][4][4];
#pragma unroll
        for (int mt = 0; mt < 2; mt++)
#pragma unroll
            for (int u = 0; u < 4; u++)
#pragma unroll
                for (int r = 0; r < 4; r++) acc[mt][u][r] = 0.f;

        // single fp16 pass
#pragma unroll
        for (int k = 0; k < 8; k++) {
            uint32_t a[2][4];
#pragma unroll
            for (int mt = 0; mt < 2; mt++)
                ldsm4t(a[mt], sb + Q_X + toff64(k * 16 + l7 + lb4 * 8, wm * 32 + mt * 16 + lb3 * 8));
            uint32_t bfr[2][4];
#pragma unroll
            for (int nt = 0; nt < 2; nt++)
                ldsm4(bfr[nt], sb + Q_W + toff(wn * 32 + nt * 16 + l7 + lb4 * 8, k * 16 + lb3 * 8));
#pragma unroll
            for (int mt = 0; mt < 2; mt++)
#pragma unroll
                for (int u = 0; u < 4; u++)
                    mma16816(acc[mt][u], a[mt], bfr[u >> 1][(u & 1) * 2],
                             bfr[u >> 1][(u & 1) * 2 + 1]);
        }
        __syncthreads();   // all MMA reads of Q_W (and Q_X for chunk 2) complete

        // prefetch next w chunk into Q_W, overlapped with the epilogue below
        if (chunk < 2) {
#pragma unroll
            for (int i = 0; i < 8; i++) {
                int lin = tid + i * 256;
                cp_async16(sb + Q_W + lin * 16, ((const uint4*)g_wsw) + (chunk + 1) * 2048 + lin);
            }
            asm volatile("cp.async.commit_group;");
        }

        // ---- epilogues ----
        if (chunk == 0) {
            // q: softmax over 32 channels per head -> global fp16 swizzled tiles
#pragma unroll
            for (int mt = 0; mt < 2; mt++)
#pragma unroll
            for (int h8 = 0; h8 < 2; h8++) {
                float e[4][2];
                float s = 0.f;
#pragma unroll
                for (int u = 0; u < 4; u++)
#pragma unroll
                    for (int j = 0; j < 2; j++) {
                        float v = __expf(acc[mt][u][h8 * 2 + j]);
                        e[u][j] = v;
                        s += v;
                    }
                s += __shfl_xor_sync(0xffffffffu, s, 1);
                s += __shfl_xor_sync(0xffffffffu, s, 2);
                const float inv = scale / s;
                const int p = wm * 32 + mt * 16 + h8 * 8 + (lane >> 2);
#pragma unroll
                for (int u = 0; u < 4; u++) {
                    int ch0 = wn * 32 + u * 8 + (lane & 3) * 2;
                    g_q[gt * 4096 + (toff(p, ch0) >> 2)] = pack_h2(e[u][0] * inv, e[u][1] * inv);
                }
            }
        } else if (chunk == 1) {
            // ek = exp(k): single fp16 into EK; sumexp partials (f32 exact)
            float sep[4][2];
#pragma unroll
            for (int u = 0; u < 4; u++) { sep[u][0] = 0.f; sep[u][1] = 0.f; }
#pragma unroll
            for (int mt = 0; mt < 2; mt++)
#pragma unroll
            for (int h8 = 0; h8 < 2; h8++) {
                const int p = wm * 32 + mt * 16 + h8 * 8 + (lane >> 2);
#pragma unroll
                for (int u = 0; u < 4; u++) {
                    float v0 = __expf(acc[mt][u][h8 * 2]);
                    float v1 = __expf(acc[mt][u][h8 * 2 + 1]);
                    sep[u][0] += v0; sep[u][1] += v1;
                    int ch0 = wn * 32 + u * 8 + (lane & 3) * 2;
                    *(uint32_t*)(smc + Q_EK + toff(p, ch0)) = pack_h2(v0, v1);
                }
            }
            float* se = (float*)(smc + Q_SE);
#pragma unroll
            for (int u = 0; u < 4; u++)
#pragma unroll
                for (int j = 0; j < 2; j++) {
                    float s = sep[u][j];
                    s += __shfl_xor_sync(0xffffffffu, s, 4);
                    s += __shfl_xor_sync(0xffffffffu, s, 8);
                    s += __shfl_xor_sync(0xffffffffu, s, 16);
                    if ((lane >> 2) == 0)
                        se[warp * 32 + u * 8 + (lane & 3) * 2 + j] = s;
                }
        } else {
            // v: single fp16 -> X (x no longer needed after the post-MMA barrier)
#pragma unroll
            for (int mt = 0; mt < 2; mt++)
#pragma unroll
            for (int h8 = 0; h8 < 2; h8++) {
                const int p = wm * 32 + mt * 16 + h8 * 8 + (lane >> 2);
#pragma unroll
                for (int u = 0; u < 4; u++) {
                    int ch0 = wn * 32 + u * 8 + (lane & 3) * 2;
                    *(uint32_t*)(smc + Q_X + toff(p, ch0)) =
                        pack_h2(acc[mt][u][h8 * 2], acc[mt][u][h8 * 2 + 1]);
                }
            }
        }

        if (chunk < 2) asm volatile("cp.async.wait_group 0;" ::: "memory");
        __syncthreads();
    }

    // ---- ctx partial: ctx_h[d][e] = sum_p ek[p,d] v[p,e]  (single fp16 pass) ----
    const int h = warp & 3, ks = warp >> 2;
    float ctx[2][4][4];
#pragma unroll
    for (int mt = 0; mt < 2; mt++)
#pragma unroll
        for (int u = 0; u < 4; u++)
#pragma unroll
            for (int r = 0; r < 4; r++) ctx[mt][u][r] = 0.f;

#pragma unroll
    for (int kk = 0; kk < 2; kk++) {
        const int p0 = ks * 32 + kk * 16;
        uint32_t a[2][4];
#pragma unroll
        for (int mt = 0; mt < 2; mt++)
            ldsm4t(a[mt], sb + Q_EK + toff(p0 + l7 + lb4 * 8, h * 32 + mt * 16 + lb3 * 8));
        uint32_t bfr[2][4];
#pragma unroll
        for (int nt = 0; nt < 2; nt++)
            ldsm4t(bfr[nt], sb + Q_X + toff(p0 + l7 + lb3 * 8, h * 32 + nt * 16 + lb4 * 8));
#pragma unroll
        for (int mt = 0; mt < 2; mt++)
#pragma unroll
            for (int u = 0; u < 4; u++)
                mma16816(ctx[mt][u], a[mt], bfr[u >> 1][(u & 1) * 2],
                         bfr[u >> 1][(u & 1) * 2 + 1]);
    }

    // two-phase ctx staging into 16KB red buffer (aliases Q_W)
    float* rb = (float*)(smc + Q_W);
    __syncthreads();
    if (ks == 0) {
#pragma unroll
        for (int mt = 0; mt < 2; mt++)
#pragma unroll
            for (int u = 0; u < 4; u++) {
                int dr = mt * 16 + (lane >> 2), e = u * 8 + (lane & 3) * 2;
                float* r = rb + h * 1024;
                r[dr * 32 + e]           = ctx[mt][u][0];
                r[dr * 32 + e + 1]       = ctx[mt][u][1];
                r[(dr + 8) * 32 + e]     = ctx[mt][u][2];
                r[(dr + 8) * 32 + e + 1] = ctx[mt][u][3];
            }
    }
    __syncthreads();
    if (ks == 1) {
#pragma unroll
        for (int mt = 0; mt < 2; mt++)
#pragma unroll
            for (int u = 0; u < 4; u++) {
                int dr = mt * 16 + (lane >> 2), e = u * 8 + (lane & 3) * 2;
                float* r = rb + h * 1024;
                r[dr * 32 + e]           += ctx[mt][u][0];
                r[dr * 32 + e + 1]       += ctx[mt][u][1];
                r[(dr + 8) * 32 + e]     += ctx[mt][u][2];
                r[(dr + 8) * 32 + e + 1] += ctx[mt][u][3];
            }
    }
    __syncthreads();

    // ---- write block partial: 2048 bf16x2 ctx + 128 f32 se ----
    {
        const size_t pbase = (size_t)gt * 2176;
#pragma unroll
        for (int i = 0; i < 8; i++) {
            int idx = tid + i * 256;            // 2048
            __nv_bfloat162 pkt = __float22bfloat162_rn(make_float2(rb[idx * 2], rb[idx * 2 + 1]));
            g_part[pbase + idx] = *(uint32_t*)&pkt;
        }
        if (tid < 128) {
            const float* se = (const float*)(smc + Q_SE);
            int wq = tid >> 5;
            float s = se[(wq * 2) * 32 + (tid & 31)] + se[(wq * 2 + 1) * 32 + (tid & 31)];
            g_part[pbase + 2048 + tid] = __float_as_uint(s);
        }
    }
}

// =============================================================================
// K2: reduce 256 tile partials per batch -> g_ctx[b][4224]
// =============================================================================
__global__ __launch_bounds__(128, 8)
void k_red()
{
    const int b = blockIdx.x / 17, g = blockIdx.x % 17;
    const int col = g * 128 + threadIdx.x;      // 0..2175
    const uint32_t* src = g_part + (size_t)b * 256 * 2176 + col;
    if (col < 2048) {
        float s0 = 0.f, s1 = 0.f;
#pragma unroll 4
        for (int t = 0; t < 256; t++) {
            uint32_t u = src[(size_t)t * 2176];
            float2 f = __bfloat1622float2(*(__nv_bfloat162*)&u);
            s0 += f.x; s1 += f.y;
        }
        g_ctx[b * 4224 + col * 2]     = s0;
        g_ctx[b * 4224 + col * 2 + 1] = s1;
    } else {
        float s = 0.f;
#pragma unroll 4
        for (int t = 0; t < 256; t++)
            s += __uint_as_float(src[(size_t)t * 2176]);
        g_ctx[b * 4224 + 4096 + (col - 2048)] = s;
    }
}

// =============================================================================
// K3: normalize ctx, build fused W2 (fp16), swizzled tiles per b.
// grid = NB*32 (4 c-rows per block).
// =============================================================================
__global__ __launch_bounds__(256, 4)
void k_w2(const float* __restrict__ w_out)
{
    __shared__ float ctxs[4224];     // [h][d][33]
    __shared__ float Ss[128];
    __shared__ float ws2[512];       // 4 c-rows x 128 ch

    const int b  = blockIdx.x >> 5;
    const int c0 = (blockIdx.x & 31) * 4;
    const int tid = threadIdx.x;

    for (int lin = tid; lin < 512; lin += 256)
        ws2[lin] = w_out[(size_t)(c0 + (lin >> 7)) * 128 + (lin & 127)];
    for (int idx = tid; idx < 4096; idx += 256) {
        int h = idx >> 10, de = idx & 1023;
        ctxs[h * 1056 + (de >> 5) * 33 + (de & 31)] = g_ctx[b * 4224 + idx];
    }
    if (tid < 128) Ss[tid] = 1.0f / g_ctx[b * 4224 + 4096 + tid];
    __syncthreads();

    {
        int cl = tid >> 6, cpp = tid & 63;       // 256 threads = 4 rows x 64 pairs
        int ch0 = cpp * 2;
        int h = ch0 >> 5, d = ch0 & 31;
        const float* cr0 = &ctxs[h * 1056 + d * 33];
        const float* cr1 = cr0 + 33;
        const float* wr  = &ws2[cl * 128 + h * 32];
        float a0 = 0.f, a1 = 0.f;
#pragma unroll
        for (int e = 0; e < 32; e++) {
            a0 = fmaf(wr[e], cr0[e], a0);
            a1 = fmaf(wr[e], cr1[e], a1);
        }
        g_W2[(uint32_t)b * 8192 + (toff(c0 + cl, ch0) >> 2)] =
            pack_h2(a0 * Ss[ch0], a1 * Ss[ch0 + 1]);
    }
}

// =============================================================================
// K4: y = W2_b @ q + b_out via fp16 mma, LayerNorm fused.  2 q-tiles per block
// (W2 loaded once), grid 2048, 2 CTAs/SM.  smem ~68 KB.
// =============================================================================
#define K3_W   0
#define K3_Q0  32768
#define K3_RS  65536
#define K3_RQ  66560
#define K3_MU  67584
#define K3_RST 67840
#define K3_SMEM 68096

__global__ __launch_bounds__(256, 2)
void k_out(const float* __restrict__ b_out, const float* __restrict__ ln_g,
           const float* __restrict__ ln_b, float* __restrict__ out)
{
    extern __shared__ char smc[];
    const uint32_t sb = smem_u32(smc);
    float* red_s = (float*)(smc + K3_RS);    // [4][64]
    float* red_q = (float*)(smc + K3_RQ);    // [4][64]
    float* mu_s  = (float*)(smc + K3_MU);    // [64]
    float* rs_s  = (float*)(smc + K3_RST);   // [64]

    const int tid = threadIdx.x;
    const int warp = tid >> 5, lane = tid & 31;
    const int wm = warp & 3, wn = warp >> 2;          // wn in {0,1}
    const int b  = blockIdx.x >> 7;
    const int tp = blockIdx.x & 127;                  // tile pair
    const size_t qt0 = ((size_t)b * 256 + tp * 2) * 1024;   // uint4 base, tile 0

#pragma unroll
    for (int i = 0; i < 8; i++) {
        int lin = tid + i * 256;              // 2048 uint4: W2 tile
        ((uint4*)(smc + K3_W))[lin] = ((const uint4*)g_W2)[(size_t)b * 2048 + lin];
    }
#pragma unroll
    for (int i = 0; i < 8; i++) {
        int lin = tid + i * 256;              // 2048 uint4: two q tiles
        ((uint4*)(smc + K3_Q0))[lin] = ((const uint4*)g_q)[qt0 + lin];
    }
    __syncthreads();

    const int l7 = lane & 7, lb3 = (lane >> 3) & 1, lb4 = (lane >> 4) & 1;

    for (int t2 = 0; t2 < 2; t2++) {
        const int n0 = (tp * 2 + t2) << 6;
        const uint32_t qB = sb + K3_Q0 + t2 * 16384;

        float acc[2][4][4];
#pragma unroll
        for (int mt = 0; mt < 2; mt++)
#pragma unroll
            for (int u = 0; u < 4; u++)
#pragma unroll
                for (int r = 0; r < 4; r++) acc[mt][u][r] = 0.f;

#pragma unroll
        for (int k = 0; k < 8; k++) {
            uint32_t a[2][4];
#pragma unroll
            for (int mt = 0; mt < 2; mt++)
                ldsm4(a[mt], sb + K3_W + toff(wm * 32 + mt * 16 + l7 + lb3 * 8, k * 16 + lb4 * 8));
            uint32_t bfr[2][4];
#pragma unroll
            for (int nt = 0; nt < 2; nt++)
                ldsm4(bfr[nt], qB + toff(wn * 32 + nt * 16 + l7 + lb4 * 8, k * 16 + lb3 * 8));
#pragma unroll
            for (int mt = 0; mt < 2; mt++)
#pragma unroll
                for (int u = 0; u < 4; u++)
                    mma16816(acc[mt][u], a[mt], bfr[u >> 1][(u & 1) * 2], bfr[u >> 1][(u & 1) * 2 + 1]);
        }

        // bias
#pragma unroll
        for (int mt = 0; mt < 2; mt++)
#pragma unroll
            for (int h8 = 0; h8 < 2; h8++) {
                const float bo = b_out[wm * 32 + mt * 16 + h8 * 8 + (lane >> 2)];
#pragma unroll
                for (int u = 0; u < 4; u++) {
                    acc[mt][u][h8 * 2]     += bo;
                    acc[mt][u][h8 * 2 + 1] += bo;
                }
            }

        // LN partials
#pragma unroll
        for (int u = 0; u < 4; u++)
#pragma unroll
            for (int j = 0; j < 2; j++) {
                float a0 = acc[0][u][j],     a1 = acc[0][u][2 + j];
                float a2 = acc[1][u][j],     a3 = acc[1][u][2 + j];
                float s = a0 + a1 + a2 + a3;
                float q = a0 * a0 + a1 * a1 + a2 * a2 + a3 * a3;
                s += __shfl_xor_sync(0xffffffffu, s, 4);
                q += __shfl_xor_sync(0xffffffffu, q, 4);
                s += __shfl_xor_sync(0xffffffffu, s, 8);
                q += __shfl_xor_sync(0xffffffffu, q, 8);
                s += __shfl_xor_sync(0xffffffffu, s, 16);
                q += __shfl_xor_sync(0xffffffffu, q, 16);
                if ((lane >> 2) == 0) {
                    int col = wn * 32 + u * 8 + (lane & 3) * 2 + j;
                    red_s[wm * 64 + col] = s;
                    red_q[wm * 64 + col] = q;
                }
            }
        __syncthreads();

        if (tid < 64) {
            float s = red_s[tid] + red_s[64 + tid] + red_s[128 + tid] + red_s[192 + tid];
            float q = red_q[tid] + red_q[64 + tid] + red_q[128 + tid] + red_q[192 + tid];
            float mu  = s * (1.0f / 128.0f);
            float var = q * (1.0f / 128.0f) - mu * mu;
            mu_s[tid] = mu;
            rs_s[tid] = rsqrtf(var + 1e-5f);
        }
        __syncthreads();

#pragma unroll
        for (int mt = 0; mt < 2; mt++)
#pragma unroll
            for (int h8 = 0; h8 < 2; h8++) {
                const int c = wm * 32 + mt * 16 + h8 * 8 + (lane >> 2);
                const float g  = ln_g[c];
                const float bb = ln_b[c];
                float* rowp = out + ((size_t)b * NCH + c) * NPOS + n0 + wn * 32 + (lane & 3) * 2;
#pragma unroll
                for (int u = 0; u < 4; u++) {
                    int col = wn * 32 + u * 8 + (lane & 3) * 2;
                    float v0 = (acc[mt][u][h8 * 2]     - mu_s[col])     * rs_s[col]     * g + bb;
                    float v1 = (acc[mt][u][h8 * 2 + 1] - mu_s[col + 1]) * rs_s[col + 1] * g + bb;
                    *(float2*)(rowp + u * 8) = make_float2(v0, v1);
                }
            }
        __syncthreads();   // red/mu buffers reused by next tile
    }
}

// =============================================================================
extern "C" void kernel_launch(void* const* d_in, const int* in_sizes, int n_in,
                              void* d_out, int out_size)
{
    const float* x     = (const float*)d_in[0];
    const float* w_qkv = (const float*)d_in[1];
    const float* w_out = (const float*)d_in[2];
    const float* b_out = (const float*)d_in[3];
    const float* ln_g  = (const float*)d_in[4];
    const float* ln_b  = (const float*)d_in[5];
    float* out = (float*)d_out;

    cudaFuncSetAttribute(k_qkv, cudaFuncAttributeMaxDynamicSharedMemorySize, Q_SMEM);
    cudaFuncSetAttribute(k_out, cudaFuncAttributeMaxDynamicSharedMemorySize, K3_SMEM);

    k_prep<<<96, 256>>>(w_qkv);
    k_qkv<<<4096, 256, Q_SMEM>>>(x);
    k_red<<<272, 128>>>();
    k_w2<<<512, 256>>>(w_out);
    k_out<<<2048, 256, K3_SMEM>>>(b_out, ln_g, ln_b, out);
}

// round 14
// speedup vs baseline: 1.2003x; 1.0857x over previous
#include <cuda_runtime.h>
#include <cuda_fp16.h>
#include <cuda_bf16.h>
#include <math.h>
#include <stdint.h>

#define NPOS 16384          // H*W
#define NB   16             // batch
#define NCH  128            // C == hidden
#define NTILE (NB * NPOS / 64)   // 4096 64-row q tiles
#define NBLK  (NB * NPOS / 128)  // 2048 k_qkv blocks (128 pos each)

// ---------------- device scratch (allocation-free rule: __device__ globals) ----
__device__ uint32_t g_q   [NTILE * 4096];   // q fp16 pairs, swizzled 64x128 tiles
__device__ uint32_t g_part[NBLK * 2176];    // per 128-pos block: 2048 bf16x2 ctx + 128 f32 se
__device__ float    g_ctx [NB * 4224];      // reduced per batch (4096 ctx + 128 se)
__device__ uint32_t g_W2  [NB * 8192];      // fused W2 fp16, swizzled 128x128 per b
__device__ uint32_t g_wsw [3 * 8192];       // w_qkv fp16, 3 swizzled 128x128 chunks

// ---------------- helpers -------------------------------------------------------
__device__ __forceinline__ uint32_t smem_u32(const void* p) {
    uint32_t a;
    asm("{ .reg .u64 t; cvta.to.shared.u64 t, %1; cvt.u32.u64 %0, t; }" : "=r"(a) : "l"(p));
    return a;
}
// swizzled byte offset within a 128-col b16 tile (256B rows)
__device__ __forceinline__ uint32_t toff(int r, int c) {
    return (uint32_t)(r * 256 + (((c >> 3) ^ (r & 7)) << 4) + ((c & 7) << 1));
}
__device__ __forceinline__ void ldsm4(uint32_t* r, uint32_t a) {
    asm volatile("ldmatrix.sync.aligned.m8n8.x4.shared.b16 {%0,%1,%2,%3}, [%4];"
                 : "=r"(r[0]), "=r"(r[1]), "=r"(r[2]), "=r"(r[3]) : "r"(a));
}
__device__ __forceinline__ void ldsm4t(uint32_t* r, uint32_t a) {
    asm volatile("ldmatrix.sync.aligned.m8n8.x4.trans.shared.b16 {%0,%1,%2,%3}, [%4];"
                 : "=r"(r[0]), "=r"(r[1]), "=r"(r[2]), "=r"(r[3]) : "r"(a));
}
__device__ __forceinline__ void mma16816(float* d, const uint32_t* a, uint32_t b0, uint32_t b1) {
    asm volatile(
        "mma.sync.aligned.m16n8k16.row.col.f32.f16.f16.f32 "
        "{%0,%1,%2,%3}, {%4,%5,%6,%7}, {%8,%9}, {%0,%1,%2,%3};"
        : "+f"(d[0]), "+f"(d[1]), "+f"(d[2]), "+f"(d[3])
        : "r"(a[0]), "r"(a[1]), "r"(a[2]), "r"(a[3]), "r"(b0), "r"(b1));
}
__device__ __forceinline__ uint32_t pack_h2(float a, float b) {
    __half2 h = __floats2half2_rn(a, b);
    return *(uint32_t*)&h;
}
__device__ __forceinline__ void cp_async16(uint32_t smem_dst, const void* gsrc) {
    asm volatile("cp.async.cg.shared.global [%0], [%1], 16;" :: "r"(smem_dst), "l"(gsrc));
}

// =============================================================================
// K0: convert w_qkv to fp16, pre-swizzled, 3 chunks of 128x128
// =============================================================================
__global__ __launch_bounds__(256)
void k_prep(const float* __restrict__ w_qkv)
{
    int idx = blockIdx.x * 256 + threadIdx.x;   // 24576 items
    int chunk = idx >> 13, rem = idx & 8191;
    int o = rem >> 6, cp = rem & 63;
    int c0 = cp * 2;
    float v0 = w_qkv[(size_t)(chunk * 128 + o) * NCH + c0];
    float v1 = w_qkv[(size_t)(chunk * 128 + o) * NCH + c0 + 1];
    g_wsw[(uint32_t)chunk * 8192 + (toff(o, c0) >> 2)] = pack_h2(v0, v1);
}

// =============================================================================
// K1: fused qkv-GEMM (fp16) + q-softmax + ctx partial, 128 positions/block.
// grid 2048, 2 CTAs/SM.  cp.async prefetch of next w chunk.
// smem: X 32K (x -> v) | W 32K (w chunk -> ctx red staging) | EK 32K | SE 2K
//       = 100,352 B
// =============================================================================
#define Q_X   0
#define Q_W   32768
#define Q_EK  65536
#define Q_SE  98304
#define Q_SMEM 100352

__global__ __launch_bounds__(256, 2)
void k_qkv(const float* __restrict__ x)
{
    extern __shared__ char smc[];
    const uint32_t sb = smem_u32(smc);
    const int tid = threadIdx.x;
    const int warp = tid >> 5, lane = tid & 31;
    const int wm = warp & 3, wn = warp >> 2;        // wm: 4x32 pos, wn: 2x64 ch

    const int b    = blockIdx.x >> 7;
    const int tile = blockIdx.x & 127;
    const int n0   = tile << 7;

    // ---- load x tile [c=128][p=128] as fp16, toff swizzle; w chunk0 copy ----
    {
        const float* xb = x + (size_t)b * NCH * NPOS + n0;
#pragma unroll
        for (int i = 0; i < 16; i++) {
            int lin = tid + i * 256;            // 4096 float4
            int c = lin >> 5, pq = lin & 31;
            float4 v = *(const float4*)(xb + (size_t)c * NPOS + pq * 4);
            uint32_t o = toff(c, pq * 4);
            *(uint32_t*)(smc + Q_X + o)     = pack_h2(v.x, v.y);
            *(uint32_t*)(smc + Q_X + o + 4) = pack_h2(v.z, v.w);
        }
#pragma unroll
        for (int i = 0; i < 8; i++) {
            int lin = tid + i * 256;            // 2048 uint4
            ((uint4*)(smc + Q_W))[lin] = ((const uint4*)g_wsw)[lin];
        }
    }
    __syncthreads();

    const int l7 = lane & 7, lb3 = (lane >> 3) & 1, lb4 = (lane >> 4) & 1;
    const float scale = 0.17677669529663687f;   // 32^-0.5

    for (int chunk = 0; chunk < 3; chunk++) {
        float acc[2][8][4];
#pragma unroll
        for (int mt = 0; mt < 2; mt++)
#pragma unroll
            for (int u = 0; u < 8; u++)
#pragma unroll
                for (int r = 0; r < 4; r++) acc[mt][u][r] = 0.f;

        // single fp16 pass: warp computes 32 pos x 64 ch
#pragma unroll
        for (int k = 0; k < 8; k++) {
            uint32_t a[2][4];
#pragma unroll
            for (int mt = 0; mt < 2; mt++)
                ldsm4t(a[mt], sb + Q_X + toff(k * 16 + l7 + lb4 * 8, wm * 32 + mt * 16 + lb3 * 8));
            uint32_t bf[4][4];
#pragma unroll
            for (int u2 = 0; u2 < 4; u2++)
                ldsm4(bf[u2], sb + Q_W + toff(wn * 64 + u2 * 16 + l7 + lb4 * 8, k * 16 + lb3 * 8));
#pragma unroll
            for (int mt = 0; mt < 2; mt++)
#pragma unroll
                for (int u = 0; u < 8; u++)
                    mma16816(acc[mt][u], a[mt], bf[u >> 1][(u & 1) * 2],
                             bf[u >> 1][(u & 1) * 2 + 1]);
        }
        __syncthreads();   // all MMA reads of Q_W (and Q_X for chunk 2) complete

        // prefetch next w chunk into Q_W, overlapped with the epilogue below
        if (chunk < 2) {
#pragma unroll
            for (int i = 0; i < 8; i++) {
                int lin = tid + i * 256;
                cp_async16(sb + Q_W + lin * 16, ((const uint4*)g_wsw) + (chunk + 1) * 2048 + lin);
            }
            asm volatile("cp.async.commit_group;");
        }

        // ---- epilogues (warp owns 32 pos x 64 ch = 2 heads) ----
        if (chunk == 0) {
            // q softmax: u<4 -> head wn*2, u>=4 -> head wn*2+1
#pragma unroll
            for (int mt = 0; mt < 2; mt++)
#pragma unroll
            for (int h8 = 0; h8 < 2; h8++) {
                float e[8][2];
                float sA = 0.f, sB = 0.f;
#pragma unroll
                for (int u = 0; u < 8; u++)
#pragma unroll
                    for (int j = 0; j < 2; j++) {
                        float v = __expf(acc[mt][u][h8 * 2 + j]);
                        e[u][j] = v;
                        if (u < 4) sA += v; else sB += v;
                    }
                sA += __shfl_xor_sync(0xffffffffu, sA, 1);
                sA += __shfl_xor_sync(0xffffffffu, sA, 2);
                sB += __shfl_xor_sync(0xffffffffu, sB, 1);
                sB += __shfl_xor_sync(0xffffffffu, sB, 2);
                const float invA = scale / sA, invB = scale / sB;
                const int p = wm * 32 + mt * 16 + h8 * 8 + (lane >> 2);
                const uint32_t gq = ((uint32_t)blockIdx.x * 2 + (p >> 6)) * 4096;
#pragma unroll
                for (int u = 0; u < 8; u++) {
                    float inv = (u < 4) ? invA : invB;
                    int ch0 = wn * 64 + u * 8 + (lane & 3) * 2;
                    g_q[gq + (toff(p & 63, ch0) >> 2)] = pack_h2(e[u][0] * inv, e[u][1] * inv);
                }
            }
        } else if (chunk == 1) {
            // ek = exp(k): fp16 into EK; sumexp partials (f32 exact)
            float sep[8][2];
#pragma unroll
            for (int u = 0; u < 8; u++) { sep[u][0] = 0.f; sep[u][1] = 0.f; }
#pragma unroll
            for (int mt = 0; mt < 2; mt++)
#pragma unroll
            for (int h8 = 0; h8 < 2; h8++) {
                const int p = wm * 32 + mt * 16 + h8 * 8 + (lane >> 2);
#pragma unroll
                for (int u = 0; u < 8; u++) {
                    float v0 = __expf(acc[mt][u][h8 * 2]);
                    float v1 = __expf(acc[mt][u][h8 * 2 + 1]);
                    sep[u][0] += v0; sep[u][1] += v1;
                    int ch0 = wn * 64 + u * 8 + (lane & 3) * 2;
                    *(uint32_t*)(smc + Q_EK + toff(p, ch0)) = pack_h2(v0, v1);
                }
            }
            float* se = (float*)(smc + Q_SE);   // [8 warps][64]
#pragma unroll
            for (int u = 0; u < 8; u++)
#pragma unroll
                for (int j = 0; j < 2; j++) {
                    float s = sep[u][j];
                    s += __shfl_xor_sync(0xffffffffu, s, 4);
                    s += __shfl_xor_sync(0xffffffffu, s, 8);
                    s += __shfl_xor_sync(0xffffffffu, s, 16);
                    if ((lane >> 2) == 0)
                        se[warp * 64 + u * 8 + (lane & 3) * 2 + j] = s;
                }
        } else {
            // v: fp16 -> X (x reads finished at the post-MMA barrier)
#pragma unroll
            for (int mt = 0; mt < 2; mt++)
#pragma unroll
            for (int h8 = 0; h8 < 2; h8++) {
                const int p = wm * 32 + mt * 16 + h8 * 8 + (lane >> 2);
#pragma unroll
                for (int u = 0; u < 8; u++) {
                    int ch0 = wn * 64 + u * 8 + (lane & 3) * 2;
                    *(uint32_t*)(smc + Q_X + toff(p, ch0)) =
                        pack_h2(acc[mt][u][h8 * 2], acc[mt][u][h8 * 2 + 1]);
                }
            }
        }

        if (chunk < 2) asm volatile("cp.async.wait_group 0;" ::: "memory");
        __syncthreads();
    }

    // ---- ctx partial: ctx_h[d][e] = sum_{p<128} ek[p,d] v[p,e] ----
    const int h = warp & 3, ks = warp >> 2;   // ks: 2 slices of 64 p
    float ctx[2][4][4];
#pragma unroll
    for (int mt = 0; mt < 2; mt++)
#pragma unroll
        for (int u = 0; u < 4; u++)
#pragma unroll
            for (int r = 0; r < 4; r++) ctx[mt][u][r] = 0.f;

#pragma unroll
    for (int kk = 0; kk < 4; kk++) {
        const int p0 = ks * 64 + kk * 16;
        uint32_t a[2][4];
#pragma unroll
        for (int mt = 0; mt < 2; mt++)
            ldsm4t(a[mt], sb + Q_EK + toff(p0 + l7 + lb4 * 8, h * 32 + mt * 16 + lb3 * 8));
        uint32_t bfr[2][4];
#pragma unroll
        for (int nt = 0; nt < 2; nt++)
            ldsm4t(bfr[nt], sb + Q_X + toff(p0 + l7 + lb3 * 8, h * 32 + nt * 16 + lb4 * 8));
#pragma unroll
        for (int mt = 0; mt < 2; mt++)
#pragma unroll
            for (int u = 0; u < 4; u++)
                mma16816(ctx[mt][u], a[mt], bfr[u >> 1][(u & 1) * 2],
                         bfr[u >> 1][(u & 1) * 2 + 1]);
    }

    // two-phase ctx staging into 16KB red buffer (aliases Q_W)
    float* rb = (float*)(smc + Q_W);
    __syncthreads();
    if (ks == 0) {
#pragma unroll
        for (int mt = 0; mt < 2; mt++)
#pragma unroll
            for (int u = 0; u < 4; u++) {
                int dr = mt * 16 + (lane >> 2), e = u * 8 + (lane & 3) * 2;
                float* r = rb + h * 1024;
                r[dr * 32 + e]           = ctx[mt][u][0];
                r[dr * 32 + e + 1]       = ctx[mt][u][1];
                r[(dr + 8) * 32 + e]     = ctx[mt][u][2];
                r[(dr + 8) * 32 + e + 1] = ctx[mt][u][3];
            }
    }
    __syncthreads();
    if (ks == 1) {
#pragma unroll
        for (int mt = 0; mt < 2; mt++)
#pragma unroll
            for (int u = 0; u < 4; u++) {
                int dr = mt * 16 + (lane >> 2), e = u * 8 + (lane & 3) * 2;
                float* r = rb + h * 1024;
                r[dr * 32 + e]           += ctx[mt][u][0];
                r[dr * 32 + e + 1]       += ctx[mt][u][1];
                r[(dr + 8) * 32 + e]     += ctx[mt][u][2];
                r[(dr + 8) * 32 + e + 1] += ctx[mt][u][3];
            }
    }
    __syncthreads();

    // ---- write block partial: 2048 bf16x2 ctx + 128 f32 se ----
    {
        const size_t pbase = (size_t)blockIdx.x * 2176;
#pragma unroll
        for (int i = 0; i < 8; i++) {
            int idx = tid + i * 256;            // 2048
            __nv_bfloat162 pkt = __float22bfloat162_rn(make_float2(rb[idx * 2], rb[idx * 2 + 1]));
            g_part[pbase + idx] = *(uint32_t*)&pkt;
        }
        if (tid < 128) {
            const float* se = (const float*)(smc + Q_SE);
            int wq = tid >> 6, c64 = tid & 63;   // ch = wq*64 + c64
            float s = se[(wq * 4 + 0) * 64 + c64] + se[(wq * 4 + 1) * 64 + c64]
                    + se[(wq * 4 + 2) * 64 + c64] + se[(wq * 4 + 3) * 64 + c64];
            g_part[pbase + 2048 + tid] = __float_as_uint(s);
        }
    }
}

// =============================================================================
// K2: reduce 128 block partials per batch -> g_ctx[b][4224]
// =============================================================================
__global__ __launch_bounds__(128, 8)
void k_red()
{
    const int b = blockIdx.x / 17, g = blockIdx.x % 17;
    const int col = g * 128 + threadIdx.x;      // 0..2175
    const uint32_t* src = g_part + (size_t)b * 128 * 2176 + col;
    if (col < 2048) {
        float s0 = 0.f, s1 = 0.f;
#pragma unroll 4
        for (int t = 0; t < 128; t++) {
            uint32_t u = src[(size_t)t * 2176];
            float2 f = __bfloat1622float2(*(__nv_bfloat162*)&u);
            s0 += f.x; s1 += f.y;
        }
        g_ctx[b * 4224 + col * 2]     = s0;
        g_ctx[b * 4224 + col * 2 + 1] = s1;
    } else {
        float s = 0.f;
#pragma unroll 4
        for (int t = 0; t < 128; t++)
            s += __uint_as_float(src[(size_t)t * 2176]);
        g_ctx[b * 4224 + 4096 + (col - 2048)] = s;
    }
}

// =============================================================================
// K3: normalize ctx, build fused W2 (fp16), swizzled tiles per b.
// grid = NB*32 (4 c-rows per block).
// =============================================================================
__global__ __launch_bounds__(256, 4)
void k_w2(const float* __restrict__ w_out)
{
    __shared__ float ctxs[4224];     // [h][d][33]
    __shared__ float Ss[128];
    __shared__ float ws2[512];       // 4 c-rows x 128 ch

    const int b  = blockIdx.x >> 5;
    const int c0 = (blockIdx.x & 31) * 4;
    const int tid = threadIdx.x;

    for (int lin = tid; lin < 512; lin += 256)
        ws2[lin] = w_out[(size_t)(c0 + (lin >> 7)) * 128 + (lin & 127)];
    for (int idx = tid; idx < 4096; idx += 256) {
        int h = idx >> 10, de = idx & 1023;
        ctxs[h * 1056 + (de >> 5) * 33 + (de & 31)] = g_ctx[b * 4224 + idx];
    }
    if (tid < 128) Ss[tid] = 1.0f / g_ctx[b * 4224 + 4096 + tid];
    __syncthreads();

    {
        int cl = tid >> 6, cpp = tid & 63;       // 256 threads = 4 rows x 64 pairs
        int ch0 = cpp * 2;
        int h = ch0 >> 5, d = ch0 & 31;
        const float* cr0 = &ctxs[h * 1056 + d * 33];
        const float* cr1 = cr0 + 33;
        const float* wr  = &ws2[cl * 128 + h * 32];
        float a0 = 0.f, a1 = 0.f;
#pragma unroll
        for (int e = 0; e < 32; e++) {
            a0 = fmaf(wr[e], cr0[e], a0);
            a1 = fmaf(wr[e], cr1[e], a1);
        }
        g_W2[(uint32_t)b * 8192 + (toff(c0 + cl, ch0) >> 2)] =
            pack_h2(a0 * Ss[ch0], a1 * Ss[ch0 + 1]);
    }
}

// =============================================================================
// K4: y = W2_b @ q + b_out via fp16 mma, LayerNorm fused.  2 q-tiles per block
// (W2 loaded once), grid 2048, 2 CTAs/SM.  smem ~68 KB.
// =============================================================================
#define K3_W   0
#define K3_Q0  32768
#define K3_RS  65536
#define K3_RQ  66560
#define K3_MU  67584
#define K3_RST 67840
#define K3_SMEM 68096

__global__ __launch_bounds__(256, 2)
void k_out(const float* __restrict__ b_out, const float* __restrict__ ln_g,
           const float* __restrict__ ln_b, float* __restrict__ out)
{
    extern __shared__ char smc[];
    const uint32_t sb = smem_u32(smc);
    float* red_s = (float*)(smc + K3_RS);    // [4][64]
    float* red_q = (float*)(smc + K3_RQ);    // [4][64]
    float* mu_s  = (float*)(smc + K3_MU);    // [64]
    float* rs_s  = (float*)(smc + K3_RST);   // [64]

    const int tid = threadIdx.x;
    const int warp = tid >> 5, lane = tid & 31;
    const int wm = warp & 3, wn = warp >> 2;          // wn in {0,1}
    const int b  = blockIdx.x >> 7;
    const int tp = blockIdx.x & 127;                  // tile pair
    const size_t qt0 = ((size_t)b * 256 + tp * 2) * 1024;   // uint4 base, tile 0

#pragma unroll
    for (int i = 0; i < 8; i++) {
        int lin = tid + i * 256;              // 2048 uint4: W2 tile
        ((uint4*)(smc + K3_W))[lin] = ((const uint4*)g_W2)[(size_t)b * 2048 + lin];
    }
#pragma unroll
    for (int i = 0; i < 8; i++) {
        int lin = tid + i * 256;              // 2048 uint4: two q tiles
        ((uint4*)(smc + K3_Q0))[lin] = ((const uint4*)g_q)[qt0 + lin];
    }
    __syncthreads();

    const int l7 = lane & 7, lb3 = (lane >> 3) & 1, lb4 = (lane >> 4) & 1;

    for (int t2 = 0; t2 < 2; t2++) {
        const int n0 = (tp * 2 + t2) << 6;
        const uint32_t qB = sb + K3_Q0 + t2 * 16384;

        float acc[2][4][4];
#pragma unroll
        for (int mt = 0; mt < 2; mt++)
#pragma unroll
            for (int u = 0; u < 4; u++)
#pragma unroll
                for (int r = 0; r < 4; r++) acc[mt][u][r] = 0.f;

#pragma unroll
        for (int k = 0; k < 8; k++) {
            uint32_t a[2][4];
#pragma unroll
            for (int mt = 0; mt < 2; mt++)
                ldsm4(a[mt], sb + K3_W + toff(wm * 32 + mt * 16 + l7 + lb3 * 8, k * 16 + lb4 * 8));
            uint32_t bfr[2][4];
#pragma unroll
            for (int nt = 0; nt < 2; nt++)
                ldsm4(bfr[nt], qB + toff(wn * 32 + nt * 16 + l7 + lb4 * 8, k * 16 + lb3 * 8));
#pragma unroll
            for (int mt = 0; mt < 2; mt++)
#pragma unroll
                for (int u = 0; u < 4; u++)
                    mma16816(acc[mt][u], a[mt], bfr[u >> 1][(u & 1) * 2], bfr[u >> 1][(u & 1) * 2 + 1]);
        }

        // bias
#pragma unroll
        for (int mt = 0; mt < 2; mt++)
#pragma unroll
            for (int h8 = 0; h8 < 2; h8++) {
                const float bo = b_out[wm * 32 + mt * 16 + h8 * 8 + (lane >> 2)];
#pragma unroll
                for (int u = 0; u < 4; u++) {
                    acc[mt][u][h8 * 2]     += bo;
                    acc[mt][u][h8 * 2 + 1] += bo;
                }
            }

        // LN partials
#pragma unroll
        for (int u = 0; u < 4; u++)
#pragma unroll
            for (int j = 0; j < 2; j++) {
                float a0 = acc[0][u][j],     a1 = acc[0][u][2 + j];
                float a2 = acc[1][u][j],     a3 = acc[1][u][2 + j];
                float s = a0 + a1 + a2 + a3;
                float q = a0 * a0 + a1 * a1 + a2 * a2 + a3 * a3;
                s += __shfl_xor_sync(0xffffffffu, s, 4);
                q += __shfl_xor_sync(0xffffffffu, q, 4);
                s += __shfl_xor_sync(0xffffffffu, s, 8);
                q += __shfl_xor_sync(0xffffffffu, q, 8);
                s += __shfl_xor_sync(0xffffffffu, s, 16);
                q += __shfl_xor_sync(0xffffffffu, q, 16);
                if ((lane >> 2) == 0) {
                    int col = wn * 32 + u * 8 + (lane & 3) * 2 + j;
                    red_s[wm * 64 + col] = s;
                    red_q[wm * 64 + col] = q;
                }
            }
        __syncthreads();

        if (tid < 64) {
            float s = red_s[tid] + red_s[64 + tid] + red_s[128 + tid] + red_s[192 + tid];
            float q = red_q[tid] + red_q[64 + tid] + red_q[128 + tid] + red_q[192 + tid];
            float mu  = s * (1.0f / 128.0f);
            float var = q * (1.0f / 128.0f) - mu * mu;
            mu_s[tid] = mu;
            rs_s[tid] = rsqrtf(var + 1e-5f);
        }
        __syncthreads();

#pragma unroll
        for (int mt = 0; mt < 2; mt++)
#pragma unroll
            for (int h8 = 0; h8 < 2; h8++) {
                const int c = wm * 32 + mt * 16 + h8 * 8 + (lane >> 2);
                const float g  = ln_g[c];
                const float bb = ln_b[c];
                float* rowp = out + ((size_t)b * NCH + c) * NPOS + n0 + wn * 32 + (lane & 3) * 2;
#pragma unroll
                for (int u = 0; u < 4; u++) {
                    int col = wn * 32 + u * 8 + (lane & 3) * 2;
                    float v0 = (acc[mt][u][h8 * 2]     - mu_s[col])     * rs_s[col]     * g + bb;
                    float v1 = (acc[mt][u][h8 * 2 + 1] - mu_s[col + 1]) * rs_s[col + 1] * g + bb;
                    *(float2*)(rowp + u * 8) = make_float2(v0, v1);
                }
            }
        __syncthreads();   // red/mu buffers reused by next tile
    }
}

// =============================================================================
extern "C" void kernel_launch(void* const* d_in, const int* in_sizes, int n_in,
                              void* d_out, int out_size)
{
    const float* x     = (const float*)d_in[0];
    const float* w_qkv = (const float*)d_in[1];
    const float* w_out = (const float*)d_in[2];
    const float* b_out = (const float*)d_in[3];
    const float* ln_g  = (const float*)d_in[4];
    const float* ln_b  = (const float*)d_in[5];
    float* out = (float*)d_out;

    cudaFuncSetAttribute(k_qkv, cudaFuncAttributeMaxDynamicSharedMemorySize, Q_SMEM);
    cudaFuncSetAttribute(k_out, cudaFuncAttributeMaxDynamicSharedMemorySize, K3_SMEM);

    k_prep<<<96, 256>>>(w_qkv);
    k_qkv<<<2048, 256, Q_SMEM>>>(x);
    k_red<<<272, 128>>>();
    k_w2<<<512, 256>>>(w_out);
    k_out<<<2048, 256, K3_SMEM>>>(b_out, ln_g, ln_b, out);
}

// round 15
// speedup vs baseline: 1.2539x; 1.0446x over previous
#include <cuda_runtime.h>
#include <cuda_fp16.h>
#include <cuda_bf16.h>
#include <math.h>
#include <stdint.h>

#define NPOS 16384          // H*W
#define NB   16             // batch
#define NCH  128            // C == hidden
#define NTILE (NB * NPOS / 64)   // 4096 64-row q tiles
#define NBLK  (NB * NPOS / 128)  // 2048 k_qkv blocks (128 pos each)

// ---------------- device scratch (allocation-free rule: __device__ globals) ----
__device__ uint32_t g_q    [NTILE * 4096];  // q fp16 pairs, swizzled 64x128 tiles
__device__ uint32_t g_part [NBLK * 2176];   // per 128-pos block: 2048 bf16x2 ctx + 128 f32 se
__device__ float    g_part2[NB * 4 * 4224]; // stage-1 reduced (f32)
__device__ float    g_ctx  [NB * 4224];     // reduced per batch (4096 ctx + 128 se)
__device__ uint32_t g_W2   [NB * 8192];     // fused W2 fp16, swizzled 128x128 per b
__device__ uint32_t g_wsw  [3 * 8192];      // w_qkv fp16, 3 swizzled 128x128 chunks

// ---------------- helpers -------------------------------------------------------
__device__ __forceinline__ uint32_t smem_u32(const void* p) {
    uint32_t a;
    asm("{ .reg .u64 t; cvta.to.shared.u64 t, %1; cvt.u32.u64 %0, t; }" : "=r"(a) : "l"(p));
    return a;
}
// swizzled byte offset within a 128-col b16 tile (256B rows)
__device__ __forceinline__ uint32_t toff(int r, int c) {
    return (uint32_t)(r * 256 + (((c >> 3) ^ (r & 7)) << 4) + ((c & 7) << 1));
}
__device__ __forceinline__ void ldsm4(uint32_t* r, uint32_t a) {
    asm volatile("ldmatrix.sync.aligned.m8n8.x4.shared.b16 {%0,%1,%2,%3}, [%4];"
                 : "=r"(r[0]), "=r"(r[1]), "=r"(r[2]), "=r"(r[3]) : "r"(a));
}
__device__ __forceinline__ void ldsm4t(uint32_t* r, uint32_t a) {
    asm volatile("ldmatrix.sync.aligned.m8n8.x4.trans.shared.b16 {%0,%1,%2,%3}, [%4];"
                 : "=r"(r[0]), "=r"(r[1]), "=r"(r[2]), "=r"(r[3]) : "r"(a));
}
__device__ __forceinline__ void mma16816(float* d, const uint32_t* a, uint32_t b0, uint32_t b1) {
    asm volatile(
        "mma.sync.aligned.m16n8k16.row.col.f32.f16.f16.f32 "
        "{%0,%1,%2,%3}, {%4,%5,%6,%7}, {%8,%9}, {%0,%1,%2,%3};"
        : "+f"(d[0]), "+f"(d[1]), "+f"(d[2]), "+f"(d[3])
        : "r"(a[0]), "r"(a[1]), "r"(a[2]), "r"(a[3]), "r"(b0), "r"(b1));
}
__device__ __forceinline__ uint32_t pack_h2(float a, float b) {
    __half2 h = __floats2half2_rn(a, b);
    return *(uint32_t*)&h;
}
__device__ __forceinline__ void cp_async16(uint32_t smem_dst, const void* gsrc) {
    asm volatile("cp.async.cg.shared.global [%0], [%1], 16;" :: "r"(smem_dst), "l"(gsrc));
}

// =============================================================================
// K0: convert w_qkv to fp16, pre-swizzled, 3 chunks of 128x128
// =============================================================================
__global__ __launch_bounds__(256)
void k_prep(const float* __restrict__ w_qkv)
{
    int idx = blockIdx.x * 256 + threadIdx.x;   // 24576 items
    int chunk = idx >> 13, rem = idx & 8191;
    int o = rem >> 6, cp = rem & 63;
    int c0 = cp * 2;
    float v0 = w_qkv[(size_t)(chunk * 128 + o) * NCH + c0];
    float v1 = w_qkv[(size_t)(chunk * 128 + o) * NCH + c0 + 1];
    g_wsw[(uint32_t)chunk * 8192 + (toff(o, c0) >> 2)] = pack_h2(v0, v1);
}

// =============================================================================
// K1: fused qkv-GEMM (fp16) + q-softmax + ctx partial, 128 positions/block.
// grid 2048, 2 CTAs/SM.  cp.async prefetch of next w chunk.  q staged in EK
// smem during chunk 0, then copied out coalesced.
// smem: X 32K (x -> v) | W 32K (w chunk -> ctx red staging) | EK 32K (q -> ek)
//       | SE 2K  = 100,352 B
// =============================================================================
#define Q_X   0
#define Q_W   32768
#define Q_EK  65536
#define Q_SE  98304
#define Q_SMEM 100352

__global__ __launch_bounds__(256, 2)
void k_qkv(const float* __restrict__ x)
{
    extern __shared__ char smc[];
    const uint32_t sb = smem_u32(smc);
    const int tid = threadIdx.x;
    const int warp = tid >> 5, lane = tid & 31;
    const int wm = warp & 3, wn = warp >> 2;        // wm: 4x32 pos, wn: 2x64 ch

    const int b    = blockIdx.x >> 7;
    const int tile = blockIdx.x & 127;
    const int n0   = tile << 7;

    // ---- load x tile [c=128][p=128] as fp16, toff swizzle; w chunk0 copy ----
    {
        const float* xb = x + (size_t)b * NCH * NPOS + n0;
#pragma unroll
        for (int i = 0; i < 16; i++) {
            int lin = tid + i * 256;            // 4096 float4
            int c = lin >> 5, pq = lin & 31;
            float4 v = *(const float4*)(xb + (size_t)c * NPOS + pq * 4);
            uint32_t o = toff(c, pq * 4);
            *(uint32_t*)(smc + Q_X + o)     = pack_h2(v.x, v.y);
            *(uint32_t*)(smc + Q_X + o + 4) = pack_h2(v.z, v.w);
        }
#pragma unroll
        for (int i = 0; i < 8; i++) {
            int lin = tid + i * 256;            // 2048 uint4
            ((uint4*)(smc + Q_W))[lin] = ((const uint4*)g_wsw)[lin];
        }
    }
    __syncthreads();

    const int l7 = lane & 7, lb3 = (lane >> 3) & 1, lb4 = (lane >> 4) & 1;
    const float scale = 0.17677669529663687f;   // 32^-0.5

    for (int chunk = 0; chunk < 3; chunk++) {
        float acc[2][8][4];
#pragma unroll
        for (int mt = 0; mt < 2; mt++)
#pragma unroll
            for (int u = 0; u < 8; u++)
#pragma unroll
                for (int r = 0; r < 4; r++) acc[mt][u][r] = 0.f;

        // single fp16 pass: warp computes 32 pos x 64 ch
#pragma unroll
        for (int k = 0; k < 8; k++) {
            uint32_t a[2][4];
#pragma unroll
            for (int mt = 0; mt < 2; mt++)
                ldsm4t(a[mt], sb + Q_X + toff(k * 16 + l7 + lb4 * 8, wm * 32 + mt * 16 + lb3 * 8));
            uint32_t bf[4][4];
#pragma unroll
            for (int u2 = 0; u2 < 4; u2++)
                ldsm4(bf[u2], sb + Q_W + toff(wn * 64 + u2 * 16 + l7 + lb4 * 8, k * 16 + lb3 * 8));
#pragma unroll
            for (int mt = 0; mt < 2; mt++)
#pragma unroll
                for (int u = 0; u < 8; u++)
                    mma16816(acc[mt][u], a[mt], bf[u >> 1][(u & 1) * 2],
                             bf[u >> 1][(u & 1) * 2 + 1]);
        }
        __syncthreads();   // all MMA reads of Q_W (and Q_X for chunk 2) complete

        // prefetch next w chunk into Q_W, overlapped with the epilogue below
        if (chunk < 2) {
#pragma unroll
            for (int i = 0; i < 8; i++) {
                int lin = tid + i * 256;
                cp_async16(sb + Q_W + lin * 16, ((const uint4*)g_wsw) + (chunk + 1) * 2048 + lin);
            }
            asm volatile("cp.async.commit_group;");
        }

        // ---- epilogues (warp owns 32 pos x 64 ch = 2 heads) ----
        if (chunk == 0) {
            // q softmax -> EK smem tile (coalesced copy-out after the barrier)
#pragma unroll
            for (int mt = 0; mt < 2; mt++)
#pragma unroll
            for (int h8 = 0; h8 < 2; h8++) {
                float e[8][2];
                float sA = 0.f, sB = 0.f;
#pragma unroll
                for (int u = 0; u < 8; u++)
#pragma unroll
                    for (int j = 0; j < 2; j++) {
                        float v = __expf(acc[mt][u][h8 * 2 + j]);
                        e[u][j] = v;
                        if (u < 4) sA += v; else sB += v;
                    }
                sA += __shfl_xor_sync(0xffffffffu, sA, 1);
                sA += __shfl_xor_sync(0xffffffffu, sA, 2);
                sB += __shfl_xor_sync(0xffffffffu, sB, 1);
                sB += __shfl_xor_sync(0xffffffffu, sB, 2);
                const float invA = scale / sA, invB = scale / sB;
                const int p = wm * 32 + mt * 16 + h8 * 8 + (lane >> 2);
#pragma unroll
                for (int u = 0; u < 8; u++) {
                    float inv = (u < 4) ? invA : invB;
                    int ch0 = wn * 64 + u * 8 + (lane & 3) * 2;
                    *(uint32_t*)(smc + Q_EK + toff(p, ch0)) = pack_h2(e[u][0] * inv, e[u][1] * inv);
                }
            }
        } else if (chunk == 1) {
            // ek = exp(k): fp16 into EK; sumexp partials (f32 exact)
            float sep[8][2];
#pragma unroll
            for (int u = 0; u < 8; u++) { sep[u][0] = 0.f; sep[u][1] = 0.f; }
#pragma unroll
            for (int mt = 0; mt < 2; mt++)
#pragma unroll
            for (int h8 = 0; h8 < 2; h8++) {
                const int p = wm * 32 + mt * 16 + h8 * 8 + (lane >> 2);
#pragma unroll
                for (int u = 0; u < 8; u++) {
                    float v0 = __expf(acc[mt][u][h8 * 2]);
                    float v1 = __expf(acc[mt][u][h8 * 2 + 1]);
                    sep[u][0] += v0; sep[u][1] += v1;
                    int ch0 = wn * 64 + u * 8 + (lane & 3) * 2;
                    *(uint32_t*)(smc + Q_EK + toff(p, ch0)) = pack_h2(v0, v1);
                }
            }
            float* se = (float*)(smc + Q_SE);   // [8 warps][64]
#pragma unroll
            for (int u = 0; u < 8; u++)
#pragma unroll
                for (int j = 0; j < 2; j++) {
                    float s = sep[u][j];
                    s += __shfl_xor_sync(0xffffffffu, s, 4);
                    s += __shfl_xor_sync(0xffffffffu, s, 8);
                    s += __shfl_xor_sync(0xffffffffu, s, 16);
                    if ((lane >> 2) == 0)
                        se[warp * 64 + u * 8 + (lane & 3) * 2 + j] = s;
                }
        } else {
            // v: fp16 -> X (x reads finished at the post-MMA barrier)
#pragma unroll
            for (int mt = 0; mt < 2; mt++)
#pragma unroll
            for (int h8 = 0; h8 < 2; h8++) {
                const int p = wm * 32 + mt * 16 + h8 * 8 + (lane >> 2);
#pragma unroll
                for (int u = 0; u < 8; u++) {
                    int ch0 = wn * 64 + u * 8 + (lane & 3) * 2;
                    *(uint32_t*)(smc + Q_X + toff(p, ch0)) =
                        pack_h2(acc[mt][u][h8 * 2], acc[mt][u][h8 * 2 + 1]);
                }
            }
        }

        if (chunk < 2) asm volatile("cp.async.wait_group 0;" ::: "memory");
        __syncthreads();

        // coalesced q copy-out (EK holds the q tile; completes before chunk-1's
        // epilogue rewrites EK, guaranteed by chunk-1's post-MMA barrier)
        if (chunk == 0) {
            const uint4* src = (const uint4*)(smc + Q_EK);
            uint4* dstg = (uint4*)g_q + (size_t)blockIdx.x * 2048;
#pragma unroll
            for (int i = 0; i < 8; i++) {
                int lin = tid + i * 256;        // 2048 uint4; 16 per 256B row
                int p = lin >> 4;
                dstg[(p >> 6) * 1024 + (p & 63) * 16 + (lin & 15)] = src[lin];
            }
        }
    }

    // ---- ctx partial: ctx_h[d][e] = sum_{p<128} ek[p,d] v[p,e] ----
    const int h = warp & 3, ks = warp >> 2;   // ks: 2 slices of 64 p
    float ctx[2][4][4];
#pragma unroll
    for (int mt = 0; mt < 2; mt++)
#pragma unroll
        for (int u = 0; u < 4; u++)
#pragma unroll
            for (int r = 0; r < 4; r++) ctx[mt][u][r] = 0.f;

#pragma unroll
    for (int kk = 0; kk < 4; kk++) {
        const int p0 = ks * 64 + kk * 16;
        uint32_t a[2][4];
#pragma unroll
        for (int mt = 0; mt < 2; mt++)
            ldsm4t(a[mt], sb + Q_EK + toff(p0 + l7 + lb4 * 8, h * 32 + mt * 16 + lb3 * 8));
        uint32_t bfr[2][4];
#pragma unroll
        for (int nt = 0; nt < 2; nt++)
            ldsm4t(bfr[nt], sb + Q_X + toff(p0 + l7 + lb3 * 8, h * 32 + nt * 16 + lb4 * 8));
#pragma unroll
        for (int mt = 0; mt < 2; mt++)
#pragma unroll
            for (int u = 0; u < 4; u++)
                mma16816(ctx[mt][u], a[mt], bfr[u >> 1][(u & 1) * 2],
                         bfr[u >> 1][(u & 1) * 2 + 1]);
    }

    // two-phase ctx staging into 16KB red buffer (aliases Q_W)
    float* rb = (float*)(smc + Q_W);
    __syncthreads();
    if (ks == 0) {
#pragma unroll
        for (int mt = 0; mt < 2; mt++)
#pragma unroll
            for (int u = 0; u < 4; u++) {
                int dr = mt * 16 + (lane >> 2), e = u * 8 + (lane & 3) * 2;
                float* r = rb + h * 1024;
                r[dr * 32 + e]           = ctx[mt][u][0];
                r[dr * 32 + e + 1]       = ctx[mt][u][1];
                r[(dr + 8) * 32 + e]     = ctx[mt][u][2];
                r[(dr + 8) * 32 + e + 1] = ctx[mt][u][3];
            }
    }
    __syncthreads();
    if (ks == 1) {
#pragma unroll
        for (int mt = 0; mt < 2; mt++)
#pragma unroll
            for (int u = 0; u < 4; u++) {
                int dr = mt * 16 + (lane >> 2), e = u * 8 + (lane & 3) * 2;
                float* r = rb + h * 1024;
                r[dr * 32 + e]           += ctx[mt][u][0];
                r[dr * 32 + e + 1]       += ctx[mt][u][1];
                r[(dr + 8) * 32 + e]     += ctx[mt][u][2];
                r[(dr + 8) * 32 + e + 1] += ctx[mt][u][3];
            }
    }
    __syncthreads();

    // ---- write block partial: 2048 bf16x2 ctx + 128 f32 se ----
    {
        const size_t pbase = (size_t)blockIdx.x * 2176;
#pragma unroll
        for (int i = 0; i < 8; i++) {
            int idx = tid + i * 256;            // 2048
            __nv_bfloat162 pkt = __float22bfloat162_rn(make_float2(rb[idx * 2], rb[idx * 2 + 1]));
            g_part[pbase + idx] = *(uint32_t*)&pkt;
        }
        if (tid < 128) {
            const float* se = (const float*)(smc + Q_SE);
            int wq = tid >> 6, c64 = tid & 63;   // ch = wq*64 + c64
            float s = se[(wq * 4 + 0) * 64 + c64] + se[(wq * 4 + 1) * 64 + c64]
                    + se[(wq * 4 + 2) * 64 + c64] + se[(wq * 4 + 3) * 64 + c64];
            g_part[pbase + 2048 + tid] = __float_as_uint(s);
        }
    }
}

// =============================================================================
// K2a: stage-1 reduce: 32 of 128 block partials -> g_part2 (f32)
// grid = 16 * 17 * 4 = 1088
// =============================================================================
__global__ __launch_bounds__(128, 8)
void k_red1()
{
    const int blk = blockIdx.x;
    const int b = blk / 68, rem = blk % 68;
    const int g = rem >> 2, q4 = rem & 3;
    const int col = g * 128 + threadIdx.x;      // 0..2175
    const uint32_t* src = g_part + ((size_t)b * 128 + q4 * 32) * 2176 + col;
    float* dst = g_part2 + ((size_t)b * 4 + q4) * 4224;
    if (col < 2048) {
        float s0 = 0.f, s1 = 0.f;
#pragma unroll 8
        for (int t = 0; t < 32; t++) {
            uint32_t u = src[(size_t)t * 2176];
            float2 f = __bfloat1622float2(*(__nv_bfloat162*)&u);
            s0 += f.x; s1 += f.y;
        }
        dst[col * 2]     = s0;
        dst[col * 2 + 1] = s1;
    } else {
        float s = 0.f;
#pragma unroll 8
        for (int t = 0; t < 32; t++)
            s += __uint_as_float(src[(size_t)t * 2176]);
        dst[4096 + (col - 2048)] = s;
    }
}

// =============================================================================
// K2b: stage-2 reduce: 4 partials -> g_ctx.  grid = 16 * 33 = 528
// =============================================================================
__global__ __launch_bounds__(128, 8)
void k_red2()
{
    const int b = blockIdx.x / 33, sc = blockIdx.x % 33;
    const int slot = sc * 128 + threadIdx.x;    // 0..4223
    const float* src = g_part2 + (size_t)b * 4 * 4224 + slot;
    g_ctx[b * 4224 + slot] = src[0] + src[4224] + src[8448] + src[12672];
}

// =============================================================================
// K3: normalize ctx, build fused W2 (fp16), swizzled tiles per b.
// grid = NB*32 (4 c-rows per block).
// =============================================================================
__global__ __launch_bounds__(256, 4)
void k_w2(const float* __restrict__ w_out)
{
    __shared__ float ctxs[4224];     // [h][d][33]
    __shared__ float Ss[128];
    __shared__ float ws2[512];       // 4 c-rows x 128 ch

    const int b  = blockIdx.x >> 5;
    const int c0 = (blockIdx.x & 31) * 4;
    const int tid = threadIdx.x;

    for (int lin = tid; lin < 512; lin += 256)
        ws2[lin] = w_out[(size_t)(c0 + (lin >> 7)) * 128 + (lin & 127)];
    for (int idx = tid; idx < 4096; idx += 256) {
        int h = idx >> 10, de = idx & 1023;
        ctxs[h * 1056 + (de >> 5) * 33 + (de & 31)] = g_ctx[b * 4224 + idx];
    }
    if (tid < 128) Ss[tid] = 1.0f / g_ctx[b * 4224 + 4096 + tid];
    __syncthreads();

    {
        int cl = tid >> 6, cpp = tid & 63;       // 256 threads = 4 rows x 64 pairs
        int ch0 = cpp * 2;
        int h = ch0 >> 5, d = ch0 & 31;
        const float* cr0 = &ctxs[h * 1056 + d * 33];
        const float* cr1 = cr0 + 33;
        const float* wr  = &ws2[cl * 128 + h * 32];
        float a0 = 0.f, a1 = 0.f;
#pragma unroll
        for (int e = 0; e < 32; e++) {
            a0 = fmaf(wr[e], cr0[e], a0);
            a1 = fmaf(wr[e], cr1[e], a1);
        }
        g_W2[(uint32_t)b * 8192 + (toff(c0 + cl, ch0) >> 2)] =
            pack_h2(a0 * Ss[ch0], a1 * Ss[ch0 + 1]);
    }
}

// =============================================================================
// K4: y = W2_b @ q + b_out via fp16 mma, LayerNorm fused.  2 q-tiles per block
// (W2 loaded once), grid 2048, 3 CTAs/SM.  smem ~68 KB.
// =============================================================================
#define K3_W   0
#define K3_Q0  32768
#define K3_RS  65536
#define K3_RQ  66560
#define K3_MU  67584
#define K3_RST 67840
#define K3_SMEM 68096

__global__ __launch_bounds__(256, 3)
void k_out(const float* __restrict__ b_out, const float* __restrict__ ln_g,
           const float* __restrict__ ln_b, float* __restrict__ out)
{
    extern __shared__ char smc[];
    const uint32_t sb = smem_u32(smc);
    float* red_s = (float*)(smc + K3_RS);    // [4][64]
    float* red_q = (float*)(smc + K3_RQ);    // [4][64]
    float* mu_s  = (float*)(smc + K3_MU);    // [64]
    float* rs_s  = (float*)(smc + K3_RST);   // [64]

    const int tid = threadIdx.x;
    const int warp = tid >> 5, lane = tid & 31;
    const int wm = warp & 3, wn = warp >> 2;          // wn in {0,1}
    const int b  = blockIdx.x >> 7;
    const int tp = blockIdx.x & 127;                  // tile pair
    const size_t qt0 = ((size_t)b * 256 + tp * 2) * 1024;   // uint4 base, tile 0

#pragma unroll
    for (int i = 0; i < 8; i++) {
        int lin = tid + i * 256;              // 2048 uint4: W2 tile
        ((uint4*)(smc + K3_W))[lin] = ((const uint4*)g_W2)[(size_t)b * 2048 + lin];
    }
#pragma unroll
    for (int i = 0; i < 8; i++) {
        int lin = tid + i * 256;              // 2048 uint4: two q tiles
        ((uint4*)(smc + K3_Q0))[lin] = ((const uint4*)g_q)[qt0 + lin];
    }
    __syncthreads();

    const int l7 = lane & 7, lb3 = (lane >> 3) & 1, lb4 = (lane >> 4) & 1;

    for (int t2 = 0; t2 < 2; t2++) {
        const int n0 = (tp * 2 + t2) << 6;
        const uint32_t qB = sb + K3_Q0 + t2 * 16384;

        float acc[2][4][4];
#pragma unroll
        for (int mt = 0; mt < 2; mt++)
#pragma unroll
            for (int u = 0; u < 4; u++)
#pragma unroll
                for (int r = 0; r < 4; r++) acc[mt][u][r] = 0.f;

#pragma unroll
        for (int k = 0; k < 8; k++) {
            uint32_t a[2][4];
#pragma unroll
            for (int mt = 0; mt < 2; mt++)
                ldsm4(a[mt], sb + K3_W + toff(wm * 32 + mt * 16 + l7 + lb3 * 8, k * 16 + lb4 * 8));
            uint32_t bfr[2][4];
#pragma unroll
            for (int nt = 0; nt < 2; nt++)
                ldsm4(bfr[nt], qB + toff(wn * 32 + nt * 16 + l7 + lb4 * 8, k * 16 + lb3 * 8));
#pragma unroll
            for (int mt = 0; mt < 2; mt++)
#pragma unroll
                for (int u = 0; u < 4; u++)
                    mma16816(acc[mt][u], a[mt], bfr[u >> 1][(u & 1) * 2], bfr[u >> 1][(u & 1) * 2 + 1]);
        }

        // bias
#pragma unroll
        for (int mt = 0; mt < 2; mt++)
#pragma unroll
            for (int h8 = 0; h8 < 2; h8++) {
                const float bo = b_out[wm * 32 + mt * 16 + h8 * 8 + (lane >> 2)];
#pragma unroll
                for (int u = 0; u < 4; u++) {
                    acc[mt][u][h8 * 2]     += bo;
                    acc[mt][u][h8 * 2 + 1] += bo;
                }
            }

        // LN partials
#pragma unroll
        for (int u = 0; u < 4; u++)
#pragma unroll
            for (int j = 0; j < 2; j++) {
                float a0 = acc[0][u][j],     a1 = acc[0][u][2 + j];
                float a2 = acc[1][u][j],     a3 = acc[1][u][2 + j];
                float s = a0 + a1 + a2 + a3;
                float q = a0 * a0 + a1 * a1 + a2 * a2 + a3 * a3;
                s += __shfl_xor_sync(0xffffffffu, s, 4);
                q += __shfl_xor_sync(0xffffffffu, q, 4);
                s += __shfl_xor_sync(0xffffffffu, s, 8);
                q += __shfl_xor_sync(0xffffffffu, q, 8);
                s += __shfl_xor_sync(0xffffffffu, s, 16);
                q += __shfl_xor_sync(0xffffffffu, q, 16);
                if ((lane >> 2) == 0) {
                    int col = wn * 32 + u * 8 + (lane & 3) * 2 + j;
                    red_s[wm * 64 + col] = s;
                    red_q[wm * 64 + col] = q;
                }
            }
        __syncthreads();

        if (tid < 64) {
            float s = red_s[tid] + red_s[64 + tid] + red_s[128 + tid] + red_s[192 + tid];
            float q = red_q[tid] + red_q[64 + tid] + red_q[128 + tid] + red_q[192 + tid];
            float mu  = s * (1.0f / 128.0f);
            float var = q * (1.0f / 128.0f) - mu * mu;
            mu_s[tid] = mu;
            rs_s[tid] = rsqrtf(var + 1e-5f);
        }
        __syncthreads();

#pragma unroll
        for (int mt = 0; mt < 2; mt++)
#pragma unroll
            for (int h8 = 0; h8 < 2; h8++) {
                const int c = wm * 32 + mt * 16 + h8 * 8 + (lane >> 2);
                const float g  = ln_g[c];
                const float bb = ln_b[c];
                float* rowp = out + ((size_t)b * NCH + c) * NPOS + n0 + wn * 32 + (lane & 3) * 2;
#pragma unroll
                for (int u = 0; u < 4; u++) {
                    int col = wn * 32 + u * 8 + (lane & 3) * 2;
                    float v0 = (acc[mt][u][h8 * 2]     - mu_s[col])     * rs_s[col]     * g + bb;
                    float v1 = (acc[mt][u][h8 * 2 + 1] - mu_s[col + 1]) * rs_s[col + 1] * g + bb;
                    *(float2*)(rowp + u * 8) = make_float2(v0, v1);
                }
            }
        __syncthreads();   // red/mu buffers reused by next tile
    }
}

// =============================================================================
extern "C" void kernel_launch(void* const* d_in, const int* in_sizes, int n_in,
                              void* d_out, int out_size)
{
    const float* x     = (const float*)d_in[0];
    const float* w_qkv = (const float*)d_in[1];
    const float* w_out = (const float*)d_in[2];
    const float* b_out = (const float*)d_in[3];
    const float* ln_g  = (const float*)d_in[4];
    const float* ln_b  = (const float*)d_in[5];
    float* out = (float*)d_out;

    cudaFuncSetAttribute(k_qkv, cudaFuncAttributeMaxDynamicSharedMemorySize, Q_SMEM);
    cudaFuncSetAttribute(k_out, cudaFuncAttributeMaxDynamicSharedMemorySize, K3_SMEM);

    k_prep<<<96, 256>>>(w_qkv);
    k_qkv<<<2048, 256, Q_SMEM>>>(x);
    k_red1<<<1088, 128>>>();
    k_red2<<<528, 128>>>();
    k_w2<<<512, 256>>>(w_out);
    k_out<<<2048, 256, K3_SMEM>>>(b_out, ln_g, ln_b, out);
}

// round 16
// speedup vs baseline: 1.2588x; 1.0039x over previous
#include <cuda_runtime.h>
#include <cuda_fp16.h>
#include <cuda_bf16.h>
#include <math.h>
#include <stdint.h>

#define NPOS 16384          // H*W
#define NB   16             // batch
#define NCH  128            // C == hidden
#define NTILE (NB * NPOS / 64)   // 4096 64-row q tiles
#define NBLK  (NB * NPOS / 128)  // 2048 k_qkv blocks (128 pos each)

// ---------------- device scratch (allocation-free rule: __device__ globals) ----
__device__ uint32_t g_q    [NTILE * 4096];  // q fp16 pairs, swizzled 64x128 tiles
__device__ uint32_t g_part [NBLK * 2176];   // per 128-pos block: 2048 bf16x2 ctx + 128 f32 se
__device__ float    g_part2[NB * 4 * 4224]; // stage-1 reduced (f32)
__device__ uint32_t g_W2   [NB * 8192];     // fused W2 fp16, swizzled 128x128 per b
__device__ uint32_t g_wsw  [3 * 8192];      // w_qkv fp16, 3 swizzled 128x128 chunks

// ---------------- helpers -------------------------------------------------------
__device__ __forceinline__ uint32_t smem_u32(const void* p) {
    uint32_t a;
    asm("{ .reg .u64 t; cvta.to.shared.u64 t, %1; cvt.u32.u64 %0, t; }" : "=r"(a) : "l"(p));
    return a;
}
// swizzled byte offset within a 128-col b16 tile (256B rows)
__device__ __forceinline__ uint32_t toff(int r, int c) {
    return (uint32_t)(r * 256 + (((c >> 3) ^ (r & 7)) << 4) + ((c & 7) << 1));
}
__device__ __forceinline__ void ldsm4(uint32_t* r, uint32_t a) {
    asm volatile("ldmatrix.sync.aligned.m8n8.x4.shared.b16 {%0,%1,%2,%3}, [%4];"
                 : "=r"(r[0]), "=r"(r[1]), "=r"(r[2]), "=r"(r[3]) : "r"(a));
}
__device__ __forceinline__ void ldsm4t(uint32_t* r, uint32_t a) {
    asm volatile("ldmatrix.sync.aligned.m8n8.x4.trans.shared.b16 {%0,%1,%2,%3}, [%4];"
                 : "=r"(r[0]), "=r"(r[1]), "=r"(r[2]), "=r"(r[3]) : "r"(a));
}
__device__ __forceinline__ void mma16816(float* d, const uint32_t* a, uint32_t b0, uint32_t b1) {
    asm volatile(
        "mma.sync.aligned.m16n8k16.row.col.f32.f16.f16.f32 "
        "{%0,%1,%2,%3}, {%4,%5,%6,%7}, {%8,%9}, {%0,%1,%2,%3};"
        : "+f"(d[0]), "+f"(d[1]), "+f"(d[2]), "+f"(d[3])
        : "r"(a[0]), "r"(a[1]), "r"(a[2]), "r"(a[3]), "r"(b0), "r"(b1));
}
__device__ __forceinline__ uint32_t pack_h2(float a, float b) {
    __half2 h = __floats2half2_rn(a, b);
    return *(uint32_t*)&h;
}
__device__ __forceinline__ void cp_async16(uint32_t smem_dst, const void* gsrc) {
    asm volatile("cp.async.cg.shared.global [%0], [%1], 16;" :: "r"(smem_dst), "l"(gsrc));
}

// =============================================================================
// K0: convert w_qkv to fp16, pre-swizzled, 3 chunks of 128x128
// =============================================================================
__global__ __launch_bounds__(256)
void k_prep(const float* __restrict__ w_qkv)
{
    int idx = blockIdx.x * 256 + threadIdx.x;   // 24576 items
    int chunk = idx >> 13, rem = idx & 8191;
    int o = rem >> 6, cp = rem & 63;
    int c0 = cp * 2;
    float v0 = w_qkv[(size_t)(chunk * 128 + o) * NCH + c0];
    float v1 = w_qkv[(size_t)(chunk * 128 + o) * NCH + c0 + 1];
    g_wsw[(uint32_t)chunk * 8192 + (toff(o, c0) >> 2)] = pack_h2(v0, v1);
}

// =============================================================================
// K1: fused qkv-GEMM (fp16) + q-softmax + ctx partial, 128 positions/block.
// grid 2048, 2 CTAs/SM.  cp.async prefetch of next w chunk.  q staged in EK
// smem during chunk 0, then copied out coalesced.
// smem: X 32K (x -> v) | W 32K (w chunk -> ctx red staging) | EK 32K (q -> ek)
//       | SE 2K  = 100,352 B
// =============================================================================
#define Q_X   0
#define Q_W   32768
#define Q_EK  65536
#define Q_SE  98304
#define Q_SMEM 100352

__global__ __launch_bounds__(256, 2)
void k_qkv(const float* __restrict__ x)
{
    extern __shared__ char smc[];
    const uint32_t sb = smem_u32(smc);
    const int tid = threadIdx.x;
    const int warp = tid >> 5, lane = tid & 31;
    const int wm = warp & 3, wn = warp >> 2;        // wm: 4x32 pos, wn: 2x64 ch

    const int b    = blockIdx.x >> 7;
    const int tile = blockIdx.x & 127;
    const int n0   = tile << 7;

    // ---- load x tile [c=128][p=128] as fp16, toff swizzle; w chunk0 copy ----
    {
        const float* xb = x + (size_t)b * NCH * NPOS + n0;
#pragma unroll
        for (int i = 0; i < 16; i++) {
            int lin = tid + i * 256;            // 4096 float4
            int c = lin >> 5, pq = lin & 31;
            float4 v = *(const float4*)(xb + (size_t)c * NPOS + pq * 4);
            uint32_t o = toff(c, pq * 4);
            *(uint32_t*)(smc + Q_X + o)     = pack_h2(v.x, v.y);
            *(uint32_t*)(smc + Q_X + o + 4) = pack_h2(v.z, v.w);
        }
#pragma unroll
        for (int i = 0; i < 8; i++) {
            int lin = tid + i * 256;            // 2048 uint4
            ((uint4*)(smc + Q_W))[lin] = ((const uint4*)g_wsw)[lin];
        }
    }
    __syncthreads();

    const int l7 = lane & 7, lb3 = (lane >> 3) & 1, lb4 = (lane >> 4) & 1;
    const float scale = 0.17677669529663687f;   // 32^-0.5

    for (int chunk = 0; chunk < 3; chunk++) {
        float acc[2][8][4];
#pragma unroll
        for (int mt = 0; mt < 2; mt++)
#pragma unroll
            for (int u = 0; u < 8; u++)
#pragma unroll
                for (int r = 0; r < 4; r++) acc[mt][u][r] = 0.f;

        // single fp16 pass: warp computes 32 pos x 64 ch
#pragma unroll
        for (int k = 0; k < 8; k++) {
            uint32_t a[2][4];
#pragma unroll
            for (int mt = 0; mt < 2; mt++)
                ldsm4t(a[mt], sb + Q_X + toff(k * 16 + l7 + lb4 * 8, wm * 32 + mt * 16 + lb3 * 8));
            uint32_t bf[4][4];
#pragma unroll
            for (int u2 = 0; u2 < 4; u2++)
                ldsm4(bf[u2], sb + Q_W + toff(wn * 64 + u2 * 16 + l7 + lb4 * 8, k * 16 + lb3 * 8));
#pragma unroll
            for (int mt = 0; mt < 2; mt++)
#pragma unroll
                for (int u = 0; u < 8; u++)
                    mma16816(acc[mt][u], a[mt], bf[u >> 1][(u & 1) * 2],
                             bf[u >> 1][(u & 1) * 2 + 1]);
        }
        __syncthreads();   // all MMA reads of Q_W (and Q_X for chunk 2) complete

        // prefetch next w chunk into Q_W, overlapped with the epilogue below
        if (chunk < 2) {
#pragma unroll
            for (int i = 0; i < 8; i++) {
                int lin = tid + i * 256;
                cp_async16(sb + Q_W + lin * 16, ((const uint4*)g_wsw) + (chunk + 1) * 2048 + lin);
            }
            asm volatile("cp.async.commit_group;");
        }

        // ---- epilogues (warp owns 32 pos x 64 ch = 2 heads) ----
        if (chunk == 0) {
            // q softmax -> EK smem tile (coalesced copy-out after the barrier)
#pragma unroll
            for (int mt = 0; mt < 2; mt++)
#pragma unroll
            for (int h8 = 0; h8 < 2; h8++) {
                float e[8][2];
                float sA = 0.f, sB = 0.f;
#pragma unroll
                for (int u = 0; u < 8; u++)
#pragma unroll
                    for (int j = 0; j < 2; j++) {
                        float v = __expf(acc[mt][u][h8 * 2 + j]);
                        e[u][j] = v;
                        if (u < 4) sA += v; else sB += v;
                    }
                sA += __shfl_xor_sync(0xffffffffu, sA, 1);
                sA += __shfl_xor_sync(0xffffffffu, sA, 2);
                sB += __shfl_xor_sync(0xffffffffu, sB, 1);
                sB += __shfl_xor_sync(0xffffffffu, sB, 2);
                const float invA = scale / sA, invB = scale / sB;
                const int p = wm * 32 + mt * 16 + h8 * 8 + (lane >> 2);
#pragma unroll
                for (int u = 0; u < 8; u++) {
                    float inv = (u < 4) ? invA : invB;
                    int ch0 = wn * 64 + u * 8 + (lane & 3) * 2;
                    *(uint32_t*)(smc + Q_EK + toff(p, ch0)) = pack_h2(e[u][0] * inv, e[u][1] * inv);
                }
            }
        } else if (chunk == 1) {
            // ek = exp(k): fp16 into EK; sumexp partials (f32 exact)
            float sep[8][2];
#pragma unroll
            for (int u = 0; u < 8; u++) { sep[u][0] = 0.f; sep[u][1] = 0.f; }
#pragma unroll
            for (int mt = 0; mt < 2; mt++)
#pragma unroll
            for (int h8 = 0; h8 < 2; h8++) {
                const int p = wm * 32 + mt * 16 + h8 * 8 + (lane >> 2);
#pragma unroll
                for (int u = 0; u < 8; u++) {
                    float v0 = __expf(acc[mt][u][h8 * 2]);
                    float v1 = __expf(acc[mt][u][h8 * 2 + 1]);
                    sep[u][0] += v0; sep[u][1] += v1;
                    int ch0 = wn * 64 + u * 8 + (lane & 3) * 2;
                    *(uint32_t*)(smc + Q_EK + toff(p, ch0)) = pack_h2(v0, v1);
                }
            }
            float* se = (float*)(smc + Q_SE);   // [8 warps][64]
#pragma unroll
            for (int u = 0; u < 8; u++)
#pragma unroll
                for (int j = 0; j < 2; j++) {
                    float s = sep[u][j];
                    s += __shfl_xor_sync(0xffffffffu, s, 4);
                    s += __shfl_xor_sync(0xffffffffu, s, 8);
                    s += __shfl_xor_sync(0xffffffffu, s, 16);
                    if ((lane >> 2) == 0)
                        se[warp * 64 + u * 8 + (lane & 3) * 2 + j] = s;
                }
        } else {
            // v: fp16 -> X (x reads finished at the post-MMA barrier)
#pragma unroll
            for (int mt = 0; mt < 2; mt++)
#pragma unroll
            for (int h8 = 0; h8 < 2; h8++) {
                const int p = wm * 32 + mt * 16 + h8 * 8 + (lane >> 2);
#pragma unroll
                for (int u = 0; u < 8; u++) {
                    int ch0 = wn * 64 + u * 8 + (lane & 3) * 2;
                    *(uint32_t*)(smc + Q_X + toff(p, ch0)) =
                        pack_h2(acc[mt][u][h8 * 2], acc[mt][u][h8 * 2 + 1]);
                }
            }
        }

        if (chunk < 2) asm volatile("cp.async.wait_group 0;" ::: "memory");
        __syncthreads();

        // coalesced q copy-out (EK holds the q tile; completes before chunk-1's
        // epilogue rewrites EK, guaranteed by chunk-1's post-MMA barrier)
        if (chunk == 0) {
            const uint4* src = (const uint4*)(smc + Q_EK);
            uint4* dstg = (uint4*)g_q + (size_t)blockIdx.x * 2048;
#pragma unroll
            for (int i = 0; i < 8; i++) {
                int lin = tid + i * 256;        // 2048 uint4; 16 per 256B row
                int p = lin >> 4;
                dstg[(p >> 6) * 1024 + (p & 63) * 16 + (lin & 15)] = src[lin];
            }
        }
    }

    // ---- ctx partial: ctx_h[d][e] = sum_{p<128} ek[p,d] v[p,e] ----
    const int h = warp & 3, ks = warp >> 2;   // ks: 2 slices of 64 p
    float ctx[2][4][4];
#pragma unroll
    for (int mt = 0; mt < 2; mt++)
#pragma unroll
        for (int u = 0; u < 4; u++)
#pragma unroll
            for (int r = 0; r < 4; r++) ctx[mt][u][r] = 0.f;

#pragma unroll
    for (int kk = 0; kk < 4; kk++) {
        const int p0 = ks * 64 + kk * 16;
        uint32_t a[2][4];
#pragma unroll
        for (int mt = 0; mt < 2; mt++)
            ldsm4t(a[mt], sb + Q_EK + toff(p0 + l7 + lb4 * 8, h * 32 + mt * 16 + lb3 * 8));
        uint32_t bfr[2][4];
#pragma unroll
        for (int nt = 0; nt < 2; nt++)
            ldsm4t(bfr[nt], sb + Q_X + toff(p0 + l7 + lb3 * 8, h * 32 + nt * 16 + lb4 * 8));
#pragma unroll
        for (int mt = 0; mt < 2; mt++)
#pragma unroll
            for (int u = 0; u < 4; u++)
                mma16816(ctx[mt][u], a[mt], bfr[u >> 1][(u & 1) * 2],
                         bfr[u >> 1][(u & 1) * 2 + 1]);
    }

    // two-phase ctx staging into 16KB red buffer (aliases Q_W)
    float* rb = (float*)(smc + Q_W);
    __syncthreads();
    if (ks == 0) {
#pragma unroll
        for (int mt = 0; mt < 2; mt++)
#pragma unroll
            for (int u = 0; u < 4; u++) {
                int dr = mt * 16 + (lane >> 2), e = u * 8 + (lane & 3) * 2;
                float* r = rb + h * 1024;
                r[dr * 32 + e]           = ctx[mt][u][0];
                r[dr * 32 + e + 1]       = ctx[mt][u][1];
                r[(dr + 8) * 32 + e]     = ctx[mt][u][2];
                r[(dr + 8) * 32 + e + 1] = ctx[mt][u][3];
            }
    }
    __syncthreads();
    if (ks == 1) {
#pragma unroll
        for (int mt = 0; mt < 2; mt++)
#pragma unroll
            for (int u = 0; u < 4; u++) {
                int dr = mt * 16 + (lane >> 2), e = u * 8 + (lane & 3) * 2;
                float* r = rb + h * 1024;
                r[dr * 32 + e]           += ctx[mt][u][0];
                r[dr * 32 + e + 1]       += ctx[mt][u][1];
                r[(dr + 8) * 32 + e]     += ctx[mt][u][2];
                r[(dr + 8) * 32 + e + 1] += ctx[mt][u][3];
            }
    }
    __syncthreads();

    // ---- write block partial: 2048 bf16x2 ctx + 128 f32 se ----
    {
        const size_t pbase = (size_t)blockIdx.x * 2176;
#pragma unroll
        for (int i = 0; i < 8; i++) {
            int idx = tid + i * 256;            // 2048
            __nv_bfloat162 pkt = __float22bfloat162_rn(make_float2(rb[idx * 2], rb[idx * 2 + 1]));
            g_part[pbase + idx] = *(uint32_t*)&pkt;
        }
        if (tid < 128) {
            const float* se = (const float*)(smc + Q_SE);
            int wq = tid >> 6, c64 = tid & 63;   // ch = wq*64 + c64
            float s = se[(wq * 4 + 0) * 64 + c64] + se[(wq * 4 + 1) * 64 + c64]
                    + se[(wq * 4 + 2) * 64 + c64] + se[(wq * 4 + 3) * 64 + c64];
            g_part[pbase + 2048 + tid] = __float_as_uint(s);
        }
    }
}

// =============================================================================
// K2: stage-1 reduce: 32 of 128 block partials -> g_part2 (f32)
// grid = 16 * 17 * 4 = 1088
// =============================================================================
__global__ __launch_bounds__(128, 8)
void k_red1()
{
    const int blk = blockIdx.x;
    const int b = blk / 68, rem = blk % 68;
    const int g = rem >> 2, q4 = rem & 3;
    const int col = g * 128 + threadIdx.x;      // 0..2175
    const uint32_t* src = g_part + ((size_t)b * 128 + q4 * 32) * 2176 + col;
    float* dst = g_part2 + ((size_t)b * 4 + q4) * 4224;
    if (col < 2048) {
        float s0 = 0.f, s1 = 0.f;
#pragma unroll 8
        for (int t = 0; t < 32; t++) {
            uint32_t u = src[(size_t)t * 2176];
            float2 f = __bfloat1622float2(*(__nv_bfloat162*)&u);
            s0 += f.x; s1 += f.y;
        }
        dst[col * 2]     = s0;
        dst[col * 2 + 1] = s1;
    } else {
        float s = 0.f;
#pragma unroll 8
        for (int t = 0; t < 32; t++)
            s += __uint_as_float(src[(size_t)t * 2176]);
        dst[4096 + (col - 2048)] = s;
    }
}

// =============================================================================
// K3: fused stage-2 reduce + normalize + build W2 (fp16), swizzled tiles per b.
// grid = NB*32 (4 c-rows per block).  Reads the 4 stage-1 partials directly.
// =============================================================================
__global__ __launch_bounds__(256, 4)
void k_w2(const float* __restrict__ w_out)
{
    __shared__ float ctxs[4224];     // [h][d][33]
    __shared__ float Ss[128];
    __shared__ float ws2[512];       // 4 c-rows x 128 ch

    const int b  = blockIdx.x >> 5;
    const int c0 = (blockIdx.x & 31) * 4;
    const int tid = threadIdx.x;
    const float* pb = g_part2 + (size_t)b * 4 * 4224;

    for (int lin = tid; lin < 512; lin += 256)
        ws2[lin] = w_out[(size_t)(c0 + (lin >> 7)) * 128 + (lin & 127)];
    for (int idx = tid; idx < 4096; idx += 256) {
        int h = idx >> 10, de = idx & 1023;
        float s = pb[idx] + pb[4224 + idx] + pb[8448 + idx] + pb[12672 + idx];
        ctxs[h * 1056 + (de >> 5) * 33 + (de & 31)] = s;
    }
    if (tid < 128) {
        float s = pb[4096 + tid] + pb[4224 + 4096 + tid]
                + pb[8448 + 4096 + tid] + pb[12672 + 4096 + tid];
        Ss[tid] = 1.0f / s;
    }
    __syncthreads();

    {
        int cl = tid >> 6, cpp = tid & 63;       // 256 threads = 4 rows x 64 pairs
        int ch0 = cpp * 2;
        int h = ch0 >> 5, d = ch0 & 31;
        const float* cr0 = &ctxs[h * 1056 + d * 33];
        const float* cr1 = cr0 + 33;
        const float* wr  = &ws2[cl * 128 + h * 32];
        float a0 = 0.f, a1 = 0.f;
#pragma unroll
        for (int e = 0; e < 32; e++) {
            a0 = fmaf(wr[e], cr0[e], a0);
            a1 = fmaf(wr[e], cr1[e], a1);
        }
        g_W2[(uint32_t)b * 8192 + (toff(c0 + cl, ch0) >> 2)] =
            pack_h2(a0 * Ss[ch0], a1 * Ss[ch0 + 1]);
    }
}

// =============================================================================
// K4: y = W2_b @ q + b_out via fp16 mma, LayerNorm fused.  2 q-tiles per block
// (W2 loaded once), grid 2048, 3 CTAs/SM.  smem ~68 KB.
// =============================================================================
#define K3_W   0
#define K3_Q0  32768
#define K3_RS  65536
#define K3_RQ  66560
#define K3_MU  67584
#define K3_RST 67840
#define K3_SMEM 68096

__global__ __launch_bounds__(256, 3)
void k_out(const float* __restrict__ b_out, const float* __restrict__ ln_g,
           const float* __restrict__ ln_b, float* __restrict__ out)
{
    extern __shared__ char smc[];
    const uint32_t sb = smem_u32(smc);
    float* red_s = (float*)(smc + K3_RS);    // [4][64]
    float* red_q = (float*)(smc + K3_RQ);    // [4][64]
    float* mu_s  = (float*)(smc + K3_MU);    // [64]
    float* rs_s  = (float*)(smc + K3_RST);   // [64]

    const int tid = threadIdx.x;
    const int warp = tid >> 5, lane = tid & 31;
    const int wm = warp & 3, wn = warp >> 2;          // wn in {0,1}
    const int b  = blockIdx.x >> 7;
    const int tp = blockIdx.x & 127;                  // tile pair
    const size_t qt0 = ((size_t)b * 256 + tp * 2) * 1024;   // uint4 base, tile 0

#pragma unroll
    for (int i = 0; i < 8; i++) {
        int lin = tid + i * 256;              // 2048 uint4: W2 tile
        ((uint4*)(smc + K3_W))[lin] = ((const uint4*)g_W2)[(size_t)b * 2048 + lin];
    }
#pragma unroll
    for (int i = 0; i < 8; i++) {
        int lin = tid + i * 256;              // 2048 uint4: two q tiles
        ((uint4*)(smc + K3_Q0))[lin] = ((const uint4*)g_q)[qt0 + lin];
    }
    __syncthreads();

    const int l7 = lane & 7, lb3 = (lane >> 3) & 1, lb4 = (lane >> 4) & 1;

    for (int t2 = 0; t2 < 2; t2++) {
        const int n0 = (tp * 2 + t2) << 6;
        const uint32_t qB = sb + K3_Q0 + t2 * 16384;

        float acc[2][4][4];
#pragma unroll
        for (int mt = 0; mt < 2; mt++)
#pragma unroll
            for (int u = 0; u < 4; u++)
#pragma unroll
                for (int r = 0; r < 4; r++) acc[mt][u][r] = 0.f;

#pragma unroll
        for (int k = 0; k < 8; k++) {
            uint32_t a[2][4];
#pragma unroll
            for (int mt = 0; mt < 2; mt++)
                ldsm4(a[mt], sb + K3_W + toff(wm * 32 + mt * 16 + l7 + lb3 * 8, k * 16 + lb4 * 8));
            uint32_t bfr[2][4];
#pragma unroll
            for (int nt = 0; nt < 2; nt++)
                ldsm4(bfr[nt], qB + toff(wn * 32 + nt * 16 + l7 + lb4 * 8, k * 16 + lb3 * 8));
#pragma unroll
            for (int mt = 0; mt < 2; mt++)
#pragma unroll
                for (int u = 0; u < 4; u++)
                    mma16816(acc[mt][u], a[mt], bfr[u >> 1][(u & 1) * 2], bfr[u >> 1][(u & 1) * 2 + 1]);
        }

        // bias
#pragma unroll
        for (int mt = 0; mt < 2; mt++)
#pragma unroll
            for (int h8 = 0; h8 < 2; h8++) {
                const float bo = b_out[wm * 32 + mt * 16 + h8 * 8 + (lane >> 2)];
#pragma unroll
                for (int u = 0; u < 4; u++) {
                    acc[mt][u][h8 * 2]     += bo;
                    acc[mt][u][h8 * 2 + 1] += bo;
                }
            }

        // LN partials
#pragma unroll
        for (int u = 0; u < 4; u++)
#pragma unroll
            for (int j = 0; j < 2; j++) {
                float a0 = acc[0][u][j],     a1 = acc[0][u][2 + j];
                float a2 = acc[1][u][j],     a3 = acc[1][u][2 + j];
                float s = a0 + a1 + a2 + a3;
                float q = a0 * a0 + a1 * a1 + a2 * a2 + a3 * a3;
                s += __shfl_xor_sync(0xffffffffu, s, 4);
                q += __shfl_xor_sync(0xffffffffu, q, 4);
                s += __shfl_xor_sync(0xffffffffu, s, 8);
                q += __shfl_xor_sync(0xffffffffu, q, 8);
                s += __shfl_xor_sync(0xffffffffu, s, 16);
                q += __shfl_xor_sync(0xffffffffu, q, 16);
                if ((lane >> 2) == 0) {
                    int col = wn * 32 + u * 8 + (lane & 3) * 2 + j;
                    red_s[wm * 64 + col] = s;
                    red_q[wm * 64 + col] = q;
                }
            }
        __syncthreads();

        if (tid < 64) {
            float s = red_s[tid] + red_s[64 + tid] + red_s[128 + tid] + red_s[192 + tid];
            float q = red_q[tid] + red_q[64 + tid] + red_q[128 + tid] + red_q[192 + tid];
            float mu  = s * (1.0f / 128.0f);
            float var = q * (1.0f / 128.0f) - mu * mu;
            mu_s[tid] = mu;
            rs_s[tid] = rsqrtf(var + 1e-5f);
        }
        __syncthreads();

#pragma unroll
        for (int mt = 0; mt < 2; mt++)
#pragma unroll
            for (int h8 = 0; h8 < 2; h8++) {
                const int c = wm * 32 + mt * 16 + h8 * 8 + (lane >> 2);
                const float g  = ln_g[c];
                const float bb = ln_b[c];
                float* rowp = out + ((size_t)b * NCH + c) * NPOS + n0 + wn * 32 + (lane & 3) * 2;
#pragma unroll
                for (int u = 0; u < 4; u++) {
                    int col = wn * 32 + u * 8 + (lane & 3) * 2;
                    float v0 = (acc[mt][u][h8 * 2]     - mu_s[col])     * rs_s[col]     * g + bb;
                    float v1 = (acc[mt][u][h8 * 2 + 1] - mu_s[col + 1]) * rs_s[col + 1] * g + bb;
                    *(float2*)(rowp + u * 8) = make_float2(v0, v1);
                }
            }
        __syncthreads();   // red/mu buffers reused by next tile
    }
}

// =============================================================================
extern "C" void kernel_launch(void* const* d_in, const int* in_sizes, int n_in,
                              void* d_out, int out_size)
{
    const float* x     = (const float*)d_in[0];
    const float* w_qkv = (const float*)d_in[1];
    const float* w_out = (const float*)d_in[2];
    const float* b_out = (const float*)d_in[3];
    const float* ln_g  = (const float*)d_in[4];
    const float* ln_b  = (const float*)d_in[5];
    float* out = (float*)d_out;

    cudaFuncSetAttribute(k_qkv, cudaFuncAttributeMaxDynamicSharedMemorySize, Q_SMEM);
    cudaFuncSetAttribute(k_out, cudaFuncAttributeMaxDynamicSharedMemorySize, K3_SMEM);

    k_prep<<<96, 256>>>(w_qkv);
    k_qkv<<<2048, 256, Q_SMEM>>>(x);
    k_red1<<<1088, 128>>>();
    k_w2<<<512, 256>>>(w_out);
    k_out<<<2048, 256, K3_SMEM>>>(b_out, ln_g, ln_b, out);
}